// round 1
// baseline (speedup 1.0000x reference)
#include <cuda_runtime.h>
#include <math.h>
#include <stdint.h>

#define MAXN 100000
#define MAXE 800000
#define H 128

// ---------------- device scratch (no runtime allocation allowed) ----------------
__device__ float g_hA[(size_t)MAXN * H];
__device__ float g_hB[(size_t)MAXN * H];
__device__ float g_neigh[(size_t)MAXN * H];
__device__ float g_m[(size_t)MAXN * H];      // also reused as a_buf (tanh output)
__device__ float g_gpre[(size_t)MAXN * H];
__device__ int   g_indeg[MAXN];
__device__ int   g_outdeg[MAXN];
__device__ int   g_cursor[MAXN];
__device__ int   g_off[MAXN];
__device__ int   g_csr[MAXE];
__device__ float g_hp[MAXN];
__device__ float g_invdeg[MAXN];
__device__ float g_scores[MAXN];
__device__ unsigned g_maxbits;

__device__ __forceinline__ float neg_inf() { return __int_as_float(0xff800000); }

__device__ __forceinline__ unsigned encf(float f) {
    unsigned u = __float_as_uint(f);
    return (u & 0x80000000u) ? ~u : (u | 0x80000000u);
}
__device__ __forceinline__ float decf(unsigned u) {
    return (u & 0x80000000u) ? __uint_as_float(u ^ 0x80000000u) : __uint_as_float(~u);
}

// ---------------- graph prep ----------------
__global__ void zero_kernel(int n) {
    int i = blockIdx.x * blockDim.x + threadIdx.x;
    if (i < n) { g_indeg[i] = 0; g_outdeg[i] = 0; g_cursor[i] = 0; }
    if (i == 0) { g_maxbits = encf(neg_inf()); }
}

__global__ void deg_kernel(const int* __restrict__ src, const int* __restrict__ dst, int e) {
    int i = blockIdx.x * blockDim.x + threadIdx.x;
    if (i < e) {
        atomicAdd(&g_indeg[dst[i]], 1);
        atomicAdd(&g_outdeg[src[i]], 1);
    }
}

__global__ void prep_kernel(int n) {
    int i = blockIdx.x * blockDim.x + threadIdx.x;
    if (i < n) {
        int d = g_indeg[i];
        g_hp[i] = d > 0 ? 1.f : 0.f;
        g_invdeg[i] = 1.f / (float)(d > 0 ? d : 1);
    }
}

// single-block exclusive scan of indeg -> g_off
__global__ void scan_kernel(int n) {
    __shared__ int sm[1024];
    __shared__ int carry;
    int tid = threadIdx.x;
    if (tid == 0) carry = 0;
    __syncthreads();
    for (int base = 0; base < n; base += 1024) {
        int i = base + tid;
        int v = (i < n) ? g_indeg[i] : 0;
        sm[tid] = v;
        __syncthreads();
        for (int off = 1; off < 1024; off <<= 1) {
            int t = (tid >= off) ? sm[tid - off] : 0;
            __syncthreads();
            sm[tid] += t;
            __syncthreads();
        }
        if (i < n) g_off[i] = carry + sm[tid] - v;
        __syncthreads();
        if (tid == 1023) carry += sm[1023];
        __syncthreads();
    }
}

__global__ void fill_kernel(const int* __restrict__ src, const int* __restrict__ dst, int e) {
    int i = blockIdx.x * blockDim.x + threadIdx.x;
    if (i < e) {
        int d = dst[i];
        int p = g_off[d] + atomicAdd(&g_cursor[d], 1);
        g_csr[p] = src[i];
    }
}

// ---------------- neighbor mean (CSR gather, one warp per node) ----------------
__global__ void neigh_kernel(const float* __restrict__ Hin, float* __restrict__ Ng, int n) {
    int gw = (blockIdx.x * blockDim.x + threadIdx.x) >> 5;
    int lane = threadIdx.x & 31;
    if (gw >= n) return;
    int start = g_off[gw];
    int deg = g_indeg[gw];
    float4 acc = make_float4(0.f, 0.f, 0.f, 0.f);
    const float4* H4 = (const float4*)Hin;
    for (int base = 0; base < deg; base += 32) {
        int e = base + lane;
        int s = (e < deg) ? g_csr[start + e] : 0;
        int cnt = min(32, deg - base);
        for (int j = 0; j < cnt; j++) {
            int sj = __shfl_sync(0xffffffffu, s, j);
            float4 hv = H4[(size_t)sj * 32 + lane];
            acc.x += hv.x; acc.y += hv.y; acc.z += hv.z; acc.w += hv.w;
        }
    }
    float iv = g_invdeg[gw];
    acc.x *= iv; acc.y *= iv; acc.z *= iv; acc.w *= iv;
    ((float4*)Ng)[(size_t)gw * 32 + lane] = acc;
}

// ---------------- generic 64x128 fp32 GEMM (K=128), weight panel in smem ----------------
// MODE 0: C = A@W + bias
// MODE 1: C += rowcoef[r] * (A@W + bias)
// MODE 2: C = tanh(A@W + bias)
#define GEMM_SMEM ((128 * 128 + 64 * 132) * 4)

template <int MODE>
__global__ __launch_bounds__(256, 2) void gemm128_kernel(
    const float* __restrict__ A, const float* __restrict__ W,
    const float* __restrict__ bias, float* __restrict__ C,
    const float* __restrict__ rowcoef, int n)
{
    extern __shared__ float smem[];
    float* Wsm = smem;              // 128*128
    float* Asm = smem + 128 * 128;  // 64 rows, stride 132

    int tid = threadIdx.x;
    // load weight panel (4096 float4 / 256 thr = 16 each)
    const float4* W4 = (const float4*)W;
    float4* Wsm4 = (float4*)Wsm;
#pragma unroll
    for (int i = 0; i < 16; i++) Wsm4[tid + 256 * i] = W4[tid + 256 * i];

    int r0 = blockIdx.x * 64;
    {
        int c4 = tid & 31;
        int rr = tid >> 5;
#pragma unroll
        for (int i = 0; i < 8; i++) {
            int r = rr + i * 8;
            float4 v = make_float4(0.f, 0.f, 0.f, 0.f);
            if (r0 + r < n) v = ((const float4*)A)[(size_t)(r0 + r) * 32 + c4];
            ((float4*)(Asm + r * 132))[c4] = v;
        }
    }
    __syncthreads();

    int tx = tid & 15, ty = tid >> 4;
    float acc[4][8];
#pragma unroll
    for (int i = 0; i < 4; i++)
#pragma unroll
        for (int j = 0; j < 8; j++) acc[i][j] = 0.f;

#pragma unroll 4
    for (int k = 0; k < 128; k++) {
        float a[4], b[8];
#pragma unroll
        for (int i = 0; i < 4; i++) a[i] = Asm[(ty * 4 + i) * 132 + k];
#pragma unroll
        for (int j = 0; j < 8; j++) b[j] = Wsm[k * 128 + tx + 16 * j];
#pragma unroll
        for (int i = 0; i < 4; i++)
#pragma unroll
            for (int j = 0; j < 8; j++) acc[i][j] = fmaf(a[i], b[j], acc[i][j]);
    }

#pragma unroll
    for (int i = 0; i < 4; i++) {
        int row = r0 + ty * 4 + i;
        if (row >= n) continue;
        float coef = (MODE == 1) ? rowcoef[row] : 1.f;
#pragma unroll
        for (int j = 0; j < 8; j++) {
            int col = tx + 16 * j;
            float v = acc[i][j] + bias[col];
            size_t idx = (size_t)row * H + col;
            if (MODE == 0) C[idx] = v;
            else if (MODE == 1) C[idx] += coef * v;
            else C[idx] = tanhf(v);
        }
    }
}

// ---------------- fused: gate GEMM (m@WgB) + sigmoid + blend + LayerNorm + ReLU ----------------
__global__ __launch_bounds__(256, 2) void gate_ln_kernel(
    const float* __restrict__ Mb, const float* __restrict__ WgB,
    const float* __restrict__ gpre, const float* __restrict__ Hin,
    const float* __restrict__ gamma, const float* __restrict__ beta,
    float* __restrict__ Hout, int n)
{
    extern __shared__ float smem[];
    float* Wsm = smem;
    float* Asm = smem + 128 * 128;  // m tile

    int tid = threadIdx.x;
    const float4* W4 = (const float4*)WgB;
    float4* Wsm4 = (float4*)Wsm;
#pragma unroll
    for (int i = 0; i < 16; i++) Wsm4[tid + 256 * i] = W4[tid + 256 * i];

    int r0 = blockIdx.x * 64;
    {
        int c4 = tid & 31;
        int rr = tid >> 5;
#pragma unroll
        for (int i = 0; i < 8; i++) {
            int r = rr + i * 8;
            float4 v = make_float4(0.f, 0.f, 0.f, 0.f);
            if (r0 + r < n) v = ((const float4*)Mb)[(size_t)(r0 + r) * 32 + c4];
            ((float4*)(Asm + r * 132))[c4] = v;
        }
    }
    __syncthreads();

    int tx = tid & 15, ty = tid >> 4;
    float acc[4][8];
#pragma unroll
    for (int i = 0; i < 4; i++)
#pragma unroll
        for (int j = 0; j < 8; j++) acc[i][j] = 0.f;

#pragma unroll 4
    for (int k = 0; k < 128; k++) {
        float a[4], b[8];
#pragma unroll
        for (int i = 0; i < 4; i++) a[i] = Asm[(ty * 4 + i) * 132 + k];
#pragma unroll
        for (int j = 0; j < 8; j++) b[j] = Wsm[k * 128 + tx + 16 * j];
#pragma unroll
        for (int i = 0; i < 4; i++)
#pragma unroll
            for (int j = 0; j < 8; j++) acc[i][j] = fmaf(a[i], b[j], acc[i][j]);
    }

    // elementwise: gate = sigmoid(gpre + acc); v = g*m + (1-g)*h; then LN + relu
#pragma unroll
    for (int i = 0; i < 4; i++) {
        int row = r0 + ty * 4 + i;
        bool valid = row < n;
        float v[8];
#pragma unroll
        for (int j = 0; j < 8; j++) {
            int col = tx + 16 * j;
            size_t idx = (size_t)row * H + col;
            float gp = valid ? gpre[idx] : 0.f;
            float hv = valid ? Hin[idx] : 0.f;
            float mv = Asm[(ty * 4 + i) * 132 + col];
            float pre = gp + acc[i][j];
            float g = 1.f / (1.f + expf(-pre));
            v[j] = g * mv + (1.f - g) * hv;
        }
        // mean over 128 (8 local + 16-lane butterfly)
        float s = 0.f;
#pragma unroll
        for (int j = 0; j < 8; j++) s += v[j];
#pragma unroll
        for (int m = 8; m >= 1; m >>= 1) s += __shfl_xor_sync(0xffffffffu, s, m);
        float mu = s * (1.f / 128.f);
        float s2 = 0.f;
#pragma unroll
        for (int j = 0; j < 8; j++) { float d = v[j] - mu; s2 += d * d; }
#pragma unroll
        for (int m = 8; m >= 1; m >>= 1) s2 += __shfl_xor_sync(0xffffffffu, s2, m);
        float rs = rsqrtf(s2 * (1.f / 128.f) + 1e-5f);
        if (valid) {
#pragma unroll
            for (int j = 0; j < 8; j++) {
                int col = tx + 16 * j;
                float o = fmaf((v[j] - mu) * rs, gamma[col], beta[col]);
                Hout[(size_t)row * H + col] = fmaxf(o, 0.f);
            }
        }
    }
}

// ---------------- pooling ----------------
__global__ void score_kernel(const float* __restrict__ Ab, const float* __restrict__ Wsc,
                             const float* __restrict__ bsc, int n)
{
    int gw = (blockIdx.x * blockDim.x + threadIdx.x) >> 5;
    int lane = threadIdx.x & 31;
    if (gw >= n) return;
    float4 av = ((const float4*)Ab)[(size_t)gw * 32 + lane];
    float4 wv = ((const float4*)Wsc)[lane];
    float p = av.x * wv.x + av.y * wv.y + av.z * wv.z + av.w * wv.w;
#pragma unroll
    for (int m = 16; m >= 1; m >>= 1) p += __shfl_xor_sync(0xffffffffu, p, m);
    if (lane == 0) {
        bool sink = (g_outdeg[gw] == 0);
        float sc = p + bsc[0];
        g_scores[gw] = sink ? sc : neg_inf();
        if (sink) atomicMax(&g_maxbits, encf(sc));
    }
}

__global__ void pool_kernel(const float* __restrict__ Hin, float* __restrict__ gout, int n) {
    __shared__ float sred[1024];
    __shared__ float sg[H];
    int tid = threadIdx.x;
    float mx = decf(g_maxbits);
    float local = 0.f;
    for (int i = tid; i < n; i += 1024) {
        float s = g_scores[i];
        if (s >= -1e30f) local += expf(s - mx);
    }
    sred[tid] = local;
    if (tid < H) sg[tid] = 0.f;
    __syncthreads();
    for (int s = 512; s > 0; s >>= 1) {
        if (tid < s) sred[tid] += sred[tid + s];
        __syncthreads();
    }
    float inv = 1.f / sred[0];
    for (int i = tid; i < n; i += 1024) {
        float s = g_scores[i];
        if (s >= -1e30f) {
            float w = expf(s - mx) * inv;
            const float* hr = Hin + (size_t)i * H;
            for (int c = 0; c < H; c++) atomicAdd(&sg[c], w * hr[c]);
        }
    }
    __syncthreads();
    if (tid < H) gout[tid] = sg[tid];
}

// ---------------- launch ----------------
extern "C" void kernel_launch(void* const* d_in, const int* in_sizes, int n_in,
                              void* d_out, int out_size)
{
    const float* node_feats = (const float*)d_in[0];
    const int*   src        = (const int*)d_in[1];
    const int*   dst        = (const int*)d_in[2];
    const float* W_in       = (const float*)d_in[3];
    const float* b_in       = (const float*)d_in[4];
    const float* Ws         = (const float*)d_in[5];
    const float* bs         = (const float*)d_in[6];
    const float* Wn         = (const float*)d_in[7];
    const float* bn         = (const float*)d_in[8];
    const float* Wg         = (const float*)d_in[9];
    const float* bg         = (const float*)d_in[10];
    const float* gamma      = (const float*)d_in[11];
    const float* beta       = (const float*)d_in[12];
    const float* W_att      = (const float*)d_in[13];
    const float* b_att      = (const float*)d_in[14];
    const float* W_score    = (const float*)d_in[15];
    const float* b_score    = (const float*)d_in[16];

    int n = in_sizes[0] / H;
    int e = in_sizes[1];
    int L = in_sizes[6] / H;

    float* out_h = (float*)d_out;
    float* out_g = out_h + (size_t)n * H;

    float *hA, *hB, *neigh, *mbuf, *gpre, *hp;
    cudaGetSymbolAddress((void**)&hA, g_hA);
    cudaGetSymbolAddress((void**)&hB, g_hB);
    cudaGetSymbolAddress((void**)&neigh, g_neigh);
    cudaGetSymbolAddress((void**)&mbuf, g_m);
    cudaGetSymbolAddress((void**)&gpre, g_gpre);
    cudaGetSymbolAddress((void**)&hp, g_hp);

    cudaFuncSetAttribute(gemm128_kernel<0>, cudaFuncAttributeMaxDynamicSharedMemorySize, GEMM_SMEM);
    cudaFuncSetAttribute(gemm128_kernel<1>, cudaFuncAttributeMaxDynamicSharedMemorySize, GEMM_SMEM);
    cudaFuncSetAttribute(gemm128_kernel<2>, cudaFuncAttributeMaxDynamicSharedMemorySize, GEMM_SMEM);
    cudaFuncSetAttribute(gate_ln_kernel,    cudaFuncAttributeMaxDynamicSharedMemorySize, GEMM_SMEM);

    int nbN = (n + 255) / 256;
    int nbE = (e + 255) / 256;
    int nbG = (n + 63) / 64;
    int nbW = (n + 7) / 8;

    // graph prep (CSR)
    zero_kernel<<<nbN, 256>>>(n);
    deg_kernel<<<nbE, 256>>>(src, dst, e);
    prep_kernel<<<nbN, 256>>>(n);
    scan_kernel<<<1, 1024>>>(n);
    fill_kernel<<<nbE, 256>>>(src, dst, e);

    // input projection
    gemm128_kernel<0><<<nbG, 256, GEMM_SMEM>>>(node_feats, W_in, b_in, hA, nullptr, n);

    float* cur = hA;
    float* other = hB;
    for (int i = 0; i < L; i++) {
        const float* Ws_i = Ws + (size_t)i * H * H;
        const float* bs_i = bs + (size_t)i * H;
        const float* Wn_i = Wn + (size_t)i * H * H;
        const float* bn_i = bn + (size_t)i * H;
        const float* Wg_i = Wg + (size_t)i * 2 * H * H;   // top half multiplies h
        const float* WgB  = Wg_i + (size_t)H * H;         // bottom half multiplies m
        const float* bg_i = bg + (size_t)i * H;
        const float* ga_i = gamma + (size_t)i * H;
        const float* be_i = beta + (size_t)i * H;

        neigh_kernel<<<nbW, 256>>>(cur, neigh, n);
        gemm128_kernel<0><<<nbG, 256, GEMM_SMEM>>>(cur, Ws_i, bs_i, mbuf, nullptr, n);
        gemm128_kernel<1><<<nbG, 256, GEMM_SMEM>>>(neigh, Wn_i, bn_i, mbuf, hp, n);
        gemm128_kernel<0><<<nbG, 256, GEMM_SMEM>>>(cur, Wg_i, bg_i, gpre, nullptr, n);

        float* outp = (i == L - 1) ? out_h : other;
        gate_ln_kernel<<<nbG, 256, GEMM_SMEM>>>(mbuf, WgB, gpre, cur, ga_i, be_i, outp, n);
        other = cur;     // old input buffer becomes scratch for next layer output
        cur = outp;
    }

    // attention pooling over sinks
    gemm128_kernel<2><<<nbG, 256, GEMM_SMEM>>>(cur, W_att, b_att, mbuf, nullptr, n);
    score_kernel<<<nbW, 256>>>(mbuf, W_score, b_score, n);
    pool_kernel<<<1, 1024>>>(cur, out_g, n);
}

// round 4
// speedup vs baseline: 1.7231x; 1.7231x over previous
#include <cuda_runtime.h>
#include <math.h>
#include <stdint.h>

#define MAXN 100000
#define MAXE 800000
#define H 128

// ---------------- device scratch ----------------
__device__ float g_hA[(size_t)MAXN * H];
__device__ float g_hB[(size_t)MAXN * H];
__device__ float g_neigh[(size_t)MAXN * H];
__device__ float g_m[(size_t)MAXN * H];
__device__ float g_gpre[(size_t)MAXN * H];
__device__ int   g_indeg[MAXN];
__device__ int   g_outdeg[MAXN];
__device__ int   g_cursor[MAXN];
__device__ int   g_off[MAXN];
__device__ int   g_csr[MAXE];
__device__ int   g_bsum[128];
__device__ float g_hp[MAXN];
__device__ float g_invdeg[MAXN];
__device__ float g_scores[MAXN];
__device__ unsigned g_maxbits;

__device__ __forceinline__ float neg_inf() { return __int_as_float(0xff800000); }
__device__ __forceinline__ unsigned encf(float f) {
    unsigned u = __float_as_uint(f);
    return (u & 0x80000000u) ? ~u : (u | 0x80000000u);
}
__device__ __forceinline__ float decf(unsigned u) {
    return (u & 0x80000000u) ? __uint_as_float(u ^ 0x80000000u) : __uint_as_float(~u);
}

// ---------------- tf32 mma.sync helpers (compute_103-safe PTX) ----------------
__device__ __forceinline__ uint32_t f2tf(float f) {
    uint32_t r;
    asm("cvt.rna.tf32.f32 %0, %1;" : "=r"(r) : "f"(f));
    return r;
}
__device__ __forceinline__ void mma1688(float* c, uint32_t a0, uint32_t a1, uint32_t a2, uint32_t a3,
                                        uint32_t b0, uint32_t b1) {
    asm volatile("mma.sync.aligned.m16n8k8.row.col.f32.tf32.tf32.f32 "
                 "{%0,%1,%2,%3}, {%4,%5,%6,%7}, {%8,%9}, {%0,%1,%2,%3};"
                 : "+f"(c[0]), "+f"(c[1]), "+f"(c[2]), "+f"(c[3])
                 : "r"(a0), "r"(a1), "r"(a2), "r"(a3), "r"(b0), "r"(b1));
}

#define A_STRIDE 132
#define W_STRIDE 136
#define SZ_A (128 * A_STRIDE)           // floats
#define SZ_W (128 * W_STRIDE)
#define SMEM_FLOATS (SZ_A + SZ_W + 512)
#define SMEM_BYTES (SMEM_FLOATS * 4)

// load 128x128 f32 tile rows [r0, r0+128) of G into smem (tf32-rounded), stride A_STRIDE
__device__ __forceinline__ void load_tile_a(const float4* __restrict__ G, int r0, int n, uint32_t* sm) {
    int t = threadIdx.x;
#pragma unroll
    for (int i = 0; i < 16; i++) {
        int g = t + i * 256;
        int row = g >> 5, c4 = g & 31;
        float4 v = make_float4(0.f, 0.f, 0.f, 0.f);
        if (r0 + row < n) v = G[(size_t)(r0 + row) * 32 + c4];
        uint32_t* p = sm + row * A_STRIDE + c4 * 4;
        p[0] = f2tf(v.x); p[1] = f2tf(v.y); p[2] = f2tf(v.z); p[3] = f2tf(v.w);
    }
}
// load 128x128 weight (row-major [k][n]) into smem, stride W_STRIDE
__device__ __forceinline__ void load_tile_w(const float4* __restrict__ G, uint32_t* sm) {
    int t = threadIdx.x;
#pragma unroll
    for (int i = 0; i < 16; i++) {
        int g = t + i * 256;
        int row = g >> 5, c4 = g & 31;
        float4 v = G[(size_t)row * 32 + c4];
        uint32_t* p = sm + row * W_STRIDE + c4 * 4;
        p[0] = f2tf(v.x); p[1] = f2tf(v.y); p[2] = f2tf(v.z); p[3] = f2tf(v.w);
    }
}

// warp-tile MMA (2Mx8N fragments per warp) over the loaded tiles: acc[2][8][4]
__device__ __forceinline__ void mma_tile(const uint32_t* Asm, const uint32_t* Wsm,
                                         float acc[2][8][4], int warpM, int warpN,
                                         int gid, int tq) {
#pragma unroll
    for (int ks = 0; ks < 16; ks++) {
        int k0 = ks * 8;
        uint32_t a[2][4];
#pragma unroll
        for (int mt = 0; mt < 2; mt++) {
            int rb = warpM * 32 + mt * 16;
            a[mt][0] = Asm[(rb + gid) * A_STRIDE + k0 + tq];
            a[mt][1] = Asm[(rb + gid + 8) * A_STRIDE + k0 + tq];
            a[mt][2] = Asm[(rb + gid) * A_STRIDE + k0 + tq + 4];
            a[mt][3] = Asm[(rb + gid + 8) * A_STRIDE + k0 + tq + 4];
        }
#pragma unroll
        for (int nt = 0; nt < 8; nt++) {
            int cb = warpN * 64 + nt * 8 + gid;
            uint32_t b0 = Wsm[(k0 + tq) * W_STRIDE + cb];
            uint32_t b1 = Wsm[(k0 + tq + 4) * W_STRIDE + cb];
#pragma unroll
            for (int mt = 0; mt < 2; mt++) mma1688(acc[mt][nt], a[mt][0], a[mt][1], a[mt][2], a[mt][3], b0, b1);
        }
    }
}

// ---------------- GEMM: C = f(A@W + bias); MODE 0 plain, 2 tanh ----------------
template <int MODE>
__global__ __launch_bounds__(256, 1) void tc_gemm(
    const float* __restrict__ A, const float* __restrict__ W,
    const float* __restrict__ bias, float* __restrict__ C, int n)
{
    extern __shared__ uint32_t smem[];
    uint32_t* Asm = smem;
    uint32_t* Wsm = smem + SZ_A;
    float* sb = (float*)(smem + SZ_A + SZ_W);

    int tid = threadIdx.x, wid = tid >> 5, lane = tid & 31;
    int warpM = wid >> 1, warpN = wid & 1, gid = lane >> 2, tq = lane & 3;
    int r0 = blockIdx.x * 128;

    load_tile_a((const float4*)A, r0, n, Asm);
    load_tile_w((const float4*)W, Wsm);
    if (tid < 128) sb[tid] = bias[tid];
    __syncthreads();

    float acc[2][8][4];
#pragma unroll
    for (int mt = 0; mt < 2; mt++)
#pragma unroll
        for (int nt = 0; nt < 8; nt++)
#pragma unroll
            for (int j = 0; j < 4; j++) acc[mt][nt][j] = 0.f;

    mma_tile(Asm, Wsm, acc, warpM, warpN, gid, tq);

#pragma unroll
    for (int mt = 0; mt < 2; mt++) {
#pragma unroll
        for (int nt = 0; nt < 8; nt++) {
            int cb = warpN * 64 + nt * 8 + 2 * tq;
            float bx = sb[cb], by = sb[cb + 1];
#pragma unroll
            for (int p = 0; p < 2; p++) {
                int row = r0 + warpM * 32 + mt * 16 + p * 8 + gid;
                if (row < n) {
                    float2 o;
                    o.x = acc[mt][nt][2 * p + 0] + bx;
                    o.y = acc[mt][nt][2 * p + 1] + by;
                    if (MODE == 2) { o.x = tanhf(o.x); o.y = tanhf(o.y); }
                    *(float2*)(C + (size_t)row * H + cb) = o;
                }
            }
        }
    }
}

// ---------------- dual GEMM: C = A1@W1 + A2@W2 + b1 + coef*b2 ----------------
__global__ __launch_bounds__(256, 1) void tc_gemm_dual(
    const float* __restrict__ A1, const float* __restrict__ W1, const float* __restrict__ b1,
    const float* __restrict__ A2, const float* __restrict__ W2, const float* __restrict__ b2,
    const float* __restrict__ coef, float* __restrict__ C, int n)
{
    extern __shared__ uint32_t smem[];
    uint32_t* Asm = smem;
    uint32_t* Wsm = smem + SZ_A;
    float* sb1 = (float*)(smem + SZ_A + SZ_W);
    float* sb2 = sb1 + 128;

    int tid = threadIdx.x, wid = tid >> 5, lane = tid & 31;
    int warpM = wid >> 1, warpN = wid & 1, gid = lane >> 2, tq = lane & 3;
    int r0 = blockIdx.x * 128;

    load_tile_a((const float4*)A1, r0, n, Asm);
    load_tile_w((const float4*)W1, Wsm);
    if (tid < 128) sb1[tid] = b1[tid];
    else if (tid < 256) sb2[tid - 128] = b2[tid - 128];
    __syncthreads();

    float acc[2][8][4];
#pragma unroll
    for (int mt = 0; mt < 2; mt++)
#pragma unroll
        for (int nt = 0; nt < 8; nt++)
#pragma unroll
            for (int j = 0; j < 4; j++) acc[mt][nt][j] = 0.f;

    mma_tile(Asm, Wsm, acc, warpM, warpN, gid, tq);
    __syncthreads();
    load_tile_a((const float4*)A2, r0, n, Asm);
    load_tile_w((const float4*)W2, Wsm);
    __syncthreads();
    mma_tile(Asm, Wsm, acc, warpM, warpN, gid, tq);

#pragma unroll
    for (int mt = 0; mt < 2; mt++) {
#pragma unroll
        for (int p = 0; p < 2; p++) {
            int row = r0 + warpM * 32 + mt * 16 + p * 8 + gid;
            if (row >= n) continue;
            float cf = coef[row];
#pragma unroll
            for (int nt = 0; nt < 8; nt++) {
                int cb = warpN * 64 + nt * 8 + 2 * tq;
                float2 o;
                o.x = acc[mt][nt][2 * p + 0] + sb1[cb] + cf * sb2[cb];
                o.y = acc[mt][nt][2 * p + 1] + sb1[cb + 1] + cf * sb2[cb + 1];
                *(float2*)(C + (size_t)row * H + cb) = o;
            }
        }
    }
}

// ---------------- fused: D = m@WgB; gate=sigmoid(D+gpre); v=g*m+(1-g)*h; LN; ReLU ----------------
// Warp tiling: 8 warps x 16 FULL rows each (row-complete => intra-quad LN reduction valid)
__global__ __launch_bounds__(256, 1) void tc_gate_ln(
    const float* __restrict__ Mb, const float* __restrict__ WgB,
    const float* __restrict__ gpre, const float* __restrict__ Hin,
    const float* __restrict__ gamma, const float* __restrict__ beta,
    float* __restrict__ Hout, int n)
{
    extern __shared__ uint32_t smem[];
    uint32_t* Asm = smem;
    uint32_t* Wsm = smem + SZ_A;
    float* sg = (float*)(smem + SZ_A + SZ_W);
    float* sbe = sg + 128;

    int tid = threadIdx.x, wid = tid >> 5, lane = tid & 31;
    int gid = lane >> 2, tq = lane & 3;
    int r0 = blockIdx.x * 128;
    int rb = wid * 16;   // this warp owns rows rb..rb+15 (full 128 cols)

    load_tile_a((const float4*)Mb, r0, n, Asm);
    load_tile_w((const float4*)WgB, Wsm);
    if (tid < 128) sg[tid] = gamma[tid];
    else if (tid < 256) sbe[tid - 128] = beta[tid - 128];
    __syncthreads();

    float acc[16][4];
#pragma unroll
    for (int nt = 0; nt < 16; nt++)
#pragma unroll
        for (int j = 0; j < 4; j++) acc[nt][j] = 0.f;

#pragma unroll
    for (int ks = 0; ks < 16; ks++) {
        int k0 = ks * 8;
        uint32_t a0 = Asm[(rb + gid) * A_STRIDE + k0 + tq];
        uint32_t a1 = Asm[(rb + gid + 8) * A_STRIDE + k0 + tq];
        uint32_t a2 = Asm[(rb + gid) * A_STRIDE + k0 + tq + 4];
        uint32_t a3 = Asm[(rb + gid + 8) * A_STRIDE + k0 + tq + 4];
#pragma unroll
        for (int nt = 0; nt < 16; nt++) {
            int cb = nt * 8 + gid;
            uint32_t b0 = Wsm[(k0 + tq) * W_STRIDE + cb];
            uint32_t b1 = Wsm[(k0 + tq + 4) * W_STRIDE + cb];
            mma1688(acc[nt], a0, a1, a2, a3, b0, b1);
        }
    }

    // gate + blend (exact fp32 operands from gmem); v back into acc; row sums per p
    float rsum[2] = {0.f, 0.f};
    float rsq[2] = {0.f, 0.f};
#pragma unroll
    for (int p = 0; p < 2; p++) {
        int row = r0 + rb + p * 8 + gid;
        if (row >= n) continue;
        const float* gp = gpre + (size_t)row * H;
        const float* hp_ = Hin + (size_t)row * H;
        const float* mp = Mb + (size_t)row * H;
#pragma unroll
        for (int nt = 0; nt < 16; nt++) {
            int cb = nt * 8 + 2 * tq;
            float2 gv = *(const float2*)(gp + cb);
            float2 hv = *(const float2*)(hp_ + cb);
            float2 mv = *(const float2*)(mp + cb);
            float pre, g, v;
            pre = acc[nt][2 * p + 0] + gv.x;
            g = 1.f / (1.f + expf(-pre));
            v = g * mv.x + (1.f - g) * hv.x;
            acc[nt][2 * p + 0] = v; rsum[p] += v; rsq[p] += v * v;
            pre = acc[nt][2 * p + 1] + gv.y;
            g = 1.f / (1.f + expf(-pre));
            v = g * mv.y + (1.f - g) * hv.y;
            acc[nt][2 * p + 1] = v; rsum[p] += v; rsq[p] += v * v;
        }
    }
    // reduce across the 4 quad lanes (tq) that share each row — now covers all 128 cols
#pragma unroll
    for (int p = 0; p < 2; p++) {
        rsum[p] += __shfl_xor_sync(0xffffffffu, rsum[p], 1);
        rsum[p] += __shfl_xor_sync(0xffffffffu, rsum[p], 2);
        rsq[p] += __shfl_xor_sync(0xffffffffu, rsq[p], 1);
        rsq[p] += __shfl_xor_sync(0xffffffffu, rsq[p], 2);
    }
#pragma unroll
    for (int p = 0; p < 2; p++) {
        int row = r0 + rb + p * 8 + gid;
        if (row >= n) continue;
        float mu = rsum[p] * (1.f / 128.f);
        float var = rsq[p] * (1.f / 128.f) - mu * mu;
        float rs = rsqrtf(var + 1e-5f);
        float* orow = Hout + (size_t)row * H;
#pragma unroll
        for (int nt = 0; nt < 16; nt++) {
            int cb = nt * 8 + 2 * tq;
            float2 o;
            o.x = fmaxf(fmaf((acc[nt][2 * p + 0] - mu) * rs, sg[cb], sbe[cb]), 0.f);
            o.y = fmaxf(fmaf((acc[nt][2 * p + 1] - mu) * rs, sg[cb + 1], sbe[cb + 1]), 0.f);
            *(float2*)(orow + cb) = o;
        }
    }
}

// ---------------- graph prep ----------------
__global__ void zero_kernel(int n) {
    int i = blockIdx.x * blockDim.x + threadIdx.x;
    if (i < n) { g_indeg[i] = 0; g_outdeg[i] = 0; g_cursor[i] = 0; }
    if (i == 0) g_maxbits = encf(neg_inf());
}
__global__ void deg_kernel(const int* __restrict__ src, const int* __restrict__ dst, int e) {
    int i = blockIdx.x * blockDim.x + threadIdx.x;
    if (i < e) { atomicAdd(&g_indeg[dst[i]], 1); atomicAdd(&g_outdeg[src[i]], 1); }
}
__global__ void prep_kernel(int n) {
    int i = blockIdx.x * blockDim.x + threadIdx.x;
    if (i < n) {
        int d = g_indeg[i];
        g_hp[i] = d > 0 ? 1.f : 0.f;
        g_invdeg[i] = 1.f / (float)(d > 0 ? d : 1);
    }
}
__global__ void scan1_kernel(int n) {
    __shared__ int sm[1024];
    int t = threadIdx.x;
    int i = blockIdx.x * 1024 + t;
    int v = (i < n) ? g_indeg[i] : 0;
    sm[t] = v;
    __syncthreads();
    for (int off = 1; off < 1024; off <<= 1) {
        int x = (t >= off) ? sm[t - off] : 0;
        __syncthreads();
        sm[t] += x;
        __syncthreads();
    }
    if (i < n) g_off[i] = sm[t] - v;
    if (t == 1023) g_bsum[blockIdx.x] = sm[1023];
}
__global__ void scan2_kernel(int nb) {
    if (threadIdx.x == 0) {
        int c = 0;
        for (int i = 0; i < nb; i++) { int x = g_bsum[i]; g_bsum[i] = c; c += x; }
    }
}
__global__ void scan3_kernel(int n) {
    int i = blockIdx.x * blockDim.x + threadIdx.x;
    if (i < n) g_off[i] += g_bsum[i >> 10];
}
__global__ void fill_kernel(const int* __restrict__ src, const int* __restrict__ dst, int e) {
    int i = blockIdx.x * blockDim.x + threadIdx.x;
    if (i < e) {
        int d = dst[i];
        int p = g_off[d] + atomicAdd(&g_cursor[d], 1);
        g_csr[p] = src[i];
    }
}

// ---------------- neighbor mean ----------------
__global__ void neigh_kernel(const float* __restrict__ Hin, float* __restrict__ Ng, int n) {
    int gw = (blockIdx.x * blockDim.x + threadIdx.x) >> 5;
    int lane = threadIdx.x & 31;
    if (gw >= n) return;
    int start = g_off[gw];
    int deg = g_indeg[gw];
    float4 acc = make_float4(0.f, 0.f, 0.f, 0.f);
    const float4* H4 = (const float4*)Hin;
    for (int base = 0; base < deg; base += 32) {
        int e = base + lane;
        int s = (e < deg) ? g_csr[start + e] : 0;
        int cnt = min(32, deg - base);
        for (int j = 0; j < cnt; j++) {
            int sj = __shfl_sync(0xffffffffu, s, j);
            float4 hv = H4[(size_t)sj * 32 + lane];
            acc.x += hv.x; acc.y += hv.y; acc.z += hv.z; acc.w += hv.w;
        }
    }
    float iv = g_invdeg[gw];
    acc.x *= iv; acc.y *= iv; acc.z *= iv; acc.w *= iv;
    ((float4*)Ng)[(size_t)gw * 32 + lane] = acc;
}

// ---------------- pooling ----------------
__global__ void score_kernel(const float* __restrict__ Ab, const float* __restrict__ Wsc,
                             const float* __restrict__ bsc, int n) {
    int gw = (blockIdx.x * blockDim.x + threadIdx.x) >> 5;
    int lane = threadIdx.x & 31;
    if (gw >= n) return;
    float4 av = ((const float4*)Ab)[(size_t)gw * 32 + lane];
    float4 wv = ((const float4*)Wsc)[lane];
    float p = av.x * wv.x + av.y * wv.y + av.z * wv.z + av.w * wv.w;
#pragma unroll
    for (int m = 16; m >= 1; m >>= 1) p += __shfl_xor_sync(0xffffffffu, p, m);
    if (lane == 0) {
        bool sink = (g_outdeg[gw] == 0);
        float sc = p + bsc[0];
        g_scores[gw] = sink ? sc : neg_inf();
        if (sink) atomicMax(&g_maxbits, encf(sc));
    }
}
__global__ void pool_kernel(const float* __restrict__ Hin, float* __restrict__ gout, int n) {
    __shared__ float sred[1024];
    __shared__ float sg[H];
    int tid = threadIdx.x;
    float mx = decf(g_maxbits);
    float local = 0.f;
    for (int i = tid; i < n; i += 1024) {
        float s = g_scores[i];
        if (s >= -1e30f) local += expf(s - mx);
    }
    sred[tid] = local;
    if (tid < H) sg[tid] = 0.f;
    __syncthreads();
    for (int s = 512; s > 0; s >>= 1) {
        if (tid < s) sred[tid] += sred[tid + s];
        __syncthreads();
    }
    float inv = 1.f / sred[0];
    for (int i = tid; i < n; i += 1024) {
        float s = g_scores[i];
        if (s >= -1e30f) {
            float w = expf(s - mx) * inv;
            const float* hr = Hin + (size_t)i * H;
            for (int c = 0; c < H; c++) atomicAdd(&sg[c], w * hr[c]);
        }
    }
    __syncthreads();
    if (tid < H) gout[tid] = sg[tid];
}

// ---------------- launch ----------------
extern "C" void kernel_launch(void* const* d_in, const int* in_sizes, int n_in,
                              void* d_out, int out_size)
{
    const float* node_feats = (const float*)d_in[0];
    const int*   src        = (const int*)d_in[1];
    const int*   dst        = (const int*)d_in[2];
    const float* W_in       = (const float*)d_in[3];
    const float* b_in       = (const float*)d_in[4];
    const float* Ws         = (const float*)d_in[5];
    const float* bs         = (const float*)d_in[6];
    const float* Wn         = (const float*)d_in[7];
    const float* bn         = (const float*)d_in[8];
    const float* Wg         = (const float*)d_in[9];
    const float* bg         = (const float*)d_in[10];
    const float* gamma      = (const float*)d_in[11];
    const float* beta       = (const float*)d_in[12];
    const float* W_att      = (const float*)d_in[13];
    const float* b_att      = (const float*)d_in[14];
    const float* W_score    = (const float*)d_in[15];
    const float* b_score    = (const float*)d_in[16];

    int n = in_sizes[0] / H;
    int e = in_sizes[1];
    int L = in_sizes[6] / H;

    float* out_h = (float*)d_out;
    float* out_g = out_h + (size_t)n * H;

    float *hA, *hB, *neigh, *mbuf, *gpre, *hp;
    cudaGetSymbolAddress((void**)&hA, g_hA);
    cudaGetSymbolAddress((void**)&hB, g_hB);
    cudaGetSymbolAddress((void**)&neigh, g_neigh);
    cudaGetSymbolAddress((void**)&mbuf, g_m);
    cudaGetSymbolAddress((void**)&gpre, g_gpre);
    cudaGetSymbolAddress((void**)&hp, g_hp);

    cudaFuncSetAttribute(tc_gemm<0>,   cudaFuncAttributeMaxDynamicSharedMemorySize, SMEM_BYTES);
    cudaFuncSetAttribute(tc_gemm<2>,   cudaFuncAttributeMaxDynamicSharedMemorySize, SMEM_BYTES);
    cudaFuncSetAttribute(tc_gemm_dual, cudaFuncAttributeMaxDynamicSharedMemorySize, SMEM_BYTES);
    cudaFuncSetAttribute(tc_gate_ln,   cudaFuncAttributeMaxDynamicSharedMemorySize, SMEM_BYTES);

    int nbN = (n + 255) / 256;
    int nbE = (e + 255) / 256;
    int nbT = (n + 127) / 128;
    int nbW = (n + 7) / 8;
    int nbS = (n + 1023) / 1024;

    // graph prep
    zero_kernel<<<nbN, 256>>>(n);
    deg_kernel<<<nbE, 256>>>(src, dst, e);
    prep_kernel<<<nbN, 256>>>(n);
    scan1_kernel<<<nbS, 1024>>>(n);
    scan2_kernel<<<1, 32>>>(nbS);
    scan3_kernel<<<nbN, 256>>>(n);
    fill_kernel<<<nbE, 256>>>(src, dst, e);

    // input projection
    tc_gemm<0><<<nbT, 256, SMEM_BYTES>>>(node_feats, W_in, b_in, hA, n);

    float* cur = hA;
    float* other = hB;
    for (int i = 0; i < L; i++) {
        const float* Ws_i = Ws + (size_t)i * H * H;
        const float* bs_i = bs + (size_t)i * H;
        const float* Wn_i = Wn + (size_t)i * H * H;
        const float* bn_i = bn + (size_t)i * H;
        const float* WgA  = Wg + (size_t)i * 2 * H * H;      // multiplies h
        const float* WgB  = WgA + (size_t)H * H;             // multiplies m
        const float* bg_i = bg + (size_t)i * H;
        const float* ga_i = gamma + (size_t)i * H;
        const float* be_i = beta + (size_t)i * H;

        neigh_kernel<<<nbW, 256>>>(cur, neigh, n);
        tc_gemm_dual<<<nbT, 256, SMEM_BYTES>>>(cur, Ws_i, bs_i, neigh, Wn_i, bn_i, hp, mbuf, n);
        tc_gemm<0><<<nbT, 256, SMEM_BYTES>>>(cur, WgA, bg_i, gpre, n);

        float* outp = (i == L - 1) ? out_h : other;
        tc_gate_ln<<<nbT, 256, SMEM_BYTES>>>(mbuf, WgB, gpre, cur, ga_i, be_i, outp, n);
        other = cur;
        cur = outp;
    }

    // attention pooling over sinks
    tc_gemm<2><<<nbT, 256, SMEM_BYTES>>>(cur, W_att, b_att, mbuf, n);
    score_kernel<<<nbW, 256>>>(mbuf, W_score, b_score, n);
    pool_kernel<<<1, 1024>>>(cur, out_g, n);
}

// round 5
// speedup vs baseline: 2.1236x; 1.2325x over previous
#include <cuda_runtime.h>
#include <math.h>
#include <stdint.h>

#define MAXN 100000
#define MAXE 800000
#define H 128

// ---------------- device scratch ----------------
__device__ float g_hA[(size_t)MAXN * H];
__device__ float g_hB[(size_t)MAXN * H];
__device__ float g_neigh[(size_t)MAXN * H];
__device__ float g_m[(size_t)MAXN * H];
__device__ int   g_indeg[MAXN];
__device__ int   g_outdeg[MAXN];
__device__ int   g_cursor[MAXN];
__device__ int   g_off[MAXN];
__device__ int   g_csr[MAXE];
__device__ int   g_bsum[128];
__device__ float g_hp[MAXN];
__device__ float g_invdeg[MAXN];
__device__ float g_scores[MAXN];
__device__ unsigned g_maxbits;

__device__ __forceinline__ float neg_inf() { return __int_as_float(0xff800000); }
__device__ __forceinline__ unsigned encf(float f) {
    unsigned u = __float_as_uint(f);
    return (u & 0x80000000u) ? ~u : (u | 0x80000000u);
}
__device__ __forceinline__ float decf(unsigned u) {
    return (u & 0x80000000u) ? __uint_as_float(u ^ 0x80000000u) : __uint_as_float(~u);
}

// ---------------- tf32 mma.sync helpers (compute_103-safe PTX) ----------------
__device__ __forceinline__ uint32_t f2tf(float f) {
    uint32_t r;
    asm("cvt.rna.tf32.f32 %0, %1;" : "=r"(r) : "f"(f));
    return r;
}
__device__ __forceinline__ void mma1688(float* c, uint32_t a0, uint32_t a1, uint32_t a2, uint32_t a3,
                                        uint32_t b0, uint32_t b1) {
    asm volatile("mma.sync.aligned.m16n8k8.row.col.f32.tf32.tf32.f32 "
                 "{%0,%1,%2,%3}, {%4,%5,%6,%7}, {%8,%9}, {%0,%1,%2,%3};"
                 : "+f"(c[0]), "+f"(c[1]), "+f"(c[2]), "+f"(c[3])
                 : "r"(a0), "r"(a1), "r"(a2), "r"(a3), "r"(b0), "r"(b1));
}

#define A_STRIDE 132
#define W_STRIDE 136
#define SZ_A (128 * A_STRIDE)           // u32 units
#define SZ_W (128 * W_STRIDE)
#define SMEM_BYTES ((SZ_A + SZ_W + 512) * 4)
// fused layer kernel smem: Acur + Wsm + Am + consts(640) + lnbuf(512)
#define LSMEM_BYTES ((2 * SZ_A + SZ_W + 640 + 512) * 4)

// load 128x128 f32 tile rows [r0, r0+128) of G into smem (tf32-rounded), stride A_STRIDE
__device__ __forceinline__ void load_tile_a(const float4* __restrict__ G, int r0, int n, uint32_t* sm) {
    int t = threadIdx.x;
#pragma unroll
    for (int i = 0; i < 16; i++) {
        int g = t + i * 256;
        int row = g >> 5, c4 = g & 31;
        float4 v = make_float4(0.f, 0.f, 0.f, 0.f);
        if (r0 + row < n) v = G[(size_t)(r0 + row) * 32 + c4];
        uint32_t* p = sm + row * A_STRIDE + c4 * 4;
        p[0] = f2tf(v.x); p[1] = f2tf(v.y); p[2] = f2tf(v.z); p[3] = f2tf(v.w);
    }
}
// load 128x128 weight (row-major [k][n]) into smem, stride W_STRIDE
__device__ __forceinline__ void load_tile_w(const float4* __restrict__ G, uint32_t* sm) {
    int t = threadIdx.x;
#pragma unroll
    for (int i = 0; i < 16; i++) {
        int g = t + i * 256;
        int row = g >> 5, c4 = g & 31;
        float4 v = G[(size_t)row * 32 + c4];
        uint32_t* p = sm + row * W_STRIDE + c4 * 4;
        p[0] = f2tf(v.x); p[1] = f2tf(v.y); p[2] = f2tf(v.z); p[3] = f2tf(v.w);
    }
}

// warp-tile MMA (2Mx8N fragments per warp): acc[2][8][4]
__device__ __forceinline__ void mma_tile(const uint32_t* Asm, const uint32_t* Wsm,
                                         float acc[2][8][4], int warpM, int warpN,
                                         int gid, int tq) {
#pragma unroll
    for (int ks = 0; ks < 16; ks++) {
        int k0 = ks * 8;
        uint32_t a[2][4];
#pragma unroll
        for (int mt = 0; mt < 2; mt++) {
            int rb = warpM * 32 + mt * 16;
            a[mt][0] = Asm[(rb + gid) * A_STRIDE + k0 + tq];
            a[mt][1] = Asm[(rb + gid + 8) * A_STRIDE + k0 + tq];
            a[mt][2] = Asm[(rb + gid) * A_STRIDE + k0 + tq + 4];
            a[mt][3] = Asm[(rb + gid + 8) * A_STRIDE + k0 + tq + 4];
        }
#pragma unroll
        for (int nt = 0; nt < 8; nt++) {
            int cb = warpN * 64 + nt * 8 + gid;
            uint32_t b0 = Wsm[(k0 + tq) * W_STRIDE + cb];
            uint32_t b1 = Wsm[(k0 + tq + 4) * W_STRIDE + cb];
#pragma unroll
            for (int mt = 0; mt < 2; mt++) mma1688(acc[mt][nt], a[mt][0], a[mt][1], a[mt][2], a[mt][3], b0, b1);
        }
    }
}

// ---------------- GEMM: C = f(A@W + bias); MODE 0 plain, 2 tanh ----------------
template <int MODE>
__global__ __launch_bounds__(256, 1) void tc_gemm(
    const float* __restrict__ A, const float* __restrict__ W,
    const float* __restrict__ bias, float* __restrict__ C, int n)
{
    extern __shared__ uint32_t smem[];
    uint32_t* Asm = smem;
    uint32_t* Wsm = smem + SZ_A;
    float* sb = (float*)(smem + SZ_A + SZ_W);

    int tid = threadIdx.x, wid = tid >> 5, lane = tid & 31;
    int warpM = wid >> 1, warpN = wid & 1, gid = lane >> 2, tq = lane & 3;
    int r0 = blockIdx.x * 128;

    load_tile_a((const float4*)A, r0, n, Asm);
    load_tile_w((const float4*)W, Wsm);
    if (tid < 128) sb[tid] = bias[tid];
    __syncthreads();

    float acc[2][8][4];
#pragma unroll
    for (int mt = 0; mt < 2; mt++)
#pragma unroll
        for (int nt = 0; nt < 8; nt++)
#pragma unroll
            for (int j = 0; j < 4; j++) acc[mt][nt][j] = 0.f;

    mma_tile(Asm, Wsm, acc, warpM, warpN, gid, tq);

#pragma unroll
    for (int mt = 0; mt < 2; mt++) {
#pragma unroll
        for (int nt = 0; nt < 8; nt++) {
            int cb = warpN * 64 + nt * 8 + 2 * tq;
            float bx = sb[cb], by = sb[cb + 1];
#pragma unroll
            for (int p = 0; p < 2; p++) {
                int row = r0 + warpM * 32 + mt * 16 + p * 8 + gid;
                if (row < n) {
                    float2 o;
                    o.x = acc[mt][nt][2 * p + 0] + bx;
                    o.y = acc[mt][nt][2 * p + 1] + by;
                    if (MODE == 2) { o.x = tanhf(o.x); o.y = tanhf(o.y); }
                    *(float2*)(C + (size_t)row * H + cb) = o;
                }
            }
        }
    }
}

// ---------------- fused layer kernel ----------------
// acc1 = cur@Ws + neigh@Wn + bs + hp*bn = m   (exact fp32 kept in regs)
// acc2 = cur@WgA + m@WgB ; gate = sigmoid(acc2+bg); v = g*m+(1-g)*h; LN; ReLU
__global__ __launch_bounds__(256, 1) void tc_layer(
    const float* __restrict__ cur, const float* __restrict__ neighb,
    const float* __restrict__ Ws, const float* __restrict__ bs,
    const float* __restrict__ Wn, const float* __restrict__ bn,
    const float* __restrict__ WgA, const float* __restrict__ WgB, const float* __restrict__ bg,
    const float* __restrict__ coef,
    const float* __restrict__ gamma, const float* __restrict__ beta,
    float* __restrict__ Hout, int n)
{
    extern __shared__ uint32_t smem[];
    uint32_t* Acur = smem;                       // cur tile (tf32)
    uint32_t* Wsm  = smem + SZ_A;                // weight panel (swapped)
    uint32_t* Am   = smem + SZ_A + SZ_W;         // neigh tile, later m tile
    float* sc  = (float*)(smem + 2 * SZ_A + SZ_W);  // bs|bn|bg|gamma|beta (5*128)
    float* lnb = sc + 640;                          // 128 rows * 2 halves * (sum,sq)

    int tid = threadIdx.x, wid = tid >> 5, lane = tid & 31;
    int warpM = wid >> 1, warpN = wid & 1, gid = lane >> 2, tq = lane & 3;
    int r0 = blockIdx.x * 128;

    load_tile_a((const float4*)cur, r0, n, Acur);
    load_tile_a((const float4*)neighb, r0, n, Am);
    load_tile_w((const float4*)Ws, Wsm);
    if (tid < 128) { sc[tid] = bs[tid]; sc[128 + tid] = bn[tid]; }
    else { int t = tid - 128; sc[256 + t] = bg[t]; sc[384 + t] = gamma[t]; sc[512 + t] = beta[t]; }
    __syncthreads();

    float acc1[2][8][4];
#pragma unroll
    for (int mt = 0; mt < 2; mt++)
#pragma unroll
        for (int nt = 0; nt < 8; nt++)
#pragma unroll
            for (int j = 0; j < 4; j++) acc1[mt][nt][j] = 0.f;

    mma_tile(Acur, Wsm, acc1, warpM, warpN, gid, tq);      // stage 1: cur@Ws
    __syncthreads();
    load_tile_w((const float4*)Wn, Wsm);
    __syncthreads();
    mma_tile(Am, Wsm, acc1, warpM, warpN, gid, tq);        // stage 2: += neigh@Wn
    __syncthreads();                                       // all reads of Am/Wn done

    // m = acc1 + bs + cf*bn ; write tf32 m over Am; also start loading WgA
#pragma unroll
    for (int mt = 0; mt < 2; mt++) {
#pragma unroll
        for (int p = 0; p < 2; p++) {
            int lrow = warpM * 32 + mt * 16 + p * 8 + gid;
            int row = r0 + lrow;
            if (row >= n) continue;
            float cf = coef[row];
#pragma unroll
            for (int nt = 0; nt < 8; nt++) {
                int cb = warpN * 64 + nt * 8 + 2 * tq;
#pragma unroll
                for (int j = 0; j < 2; j++) {
                    float v = acc1[mt][nt][2 * p + j] + sc[cb + j] + cf * sc[128 + cb + j];
                    acc1[mt][nt][2 * p + j] = v;
                    Am[lrow * A_STRIDE + cb + j] = f2tf(v);
                }
            }
        }
    }
    load_tile_w((const float4*)WgA, Wsm);
    __syncthreads();

    float acc2[2][8][4];
#pragma unroll
    for (int mt = 0; mt < 2; mt++)
#pragma unroll
        for (int nt = 0; nt < 8; nt++)
#pragma unroll
            for (int j = 0; j < 4; j++) acc2[mt][nt][j] = 0.f;

    mma_tile(Acur, Wsm, acc2, warpM, warpN, gid, tq);      // stage 3: cur@WgA
    __syncthreads();
    load_tile_w((const float4*)WgB, Wsm);
    __syncthreads();
    mma_tile(Am, Wsm, acc2, warpM, warpN, gid, tq);        // stage 4: += m@WgB

    // epilogue: gate + blend + LN + ReLU
    float rsum[2][2] = {{0.f, 0.f}, {0.f, 0.f}};
    float rsq[2][2] = {{0.f, 0.f}, {0.f, 0.f}};
#pragma unroll
    for (int mt = 0; mt < 2; mt++) {
#pragma unroll
        for (int p = 0; p < 2; p++) {
            int row = r0 + warpM * 32 + mt * 16 + p * 8 + gid;
            if (row >= n) continue;
            const float* hrow = cur + (size_t)row * H;
#pragma unroll
            for (int nt = 0; nt < 8; nt++) {
                int cb = warpN * 64 + nt * 8 + 2 * tq;
                float2 hv = *(const float2*)(hrow + cb);
                float pre, g, v;
                pre = acc2[mt][nt][2 * p + 0] + sc[256 + cb];
                g = 1.f / (1.f + expf(-pre));
                v = g * acc1[mt][nt][2 * p + 0] + (1.f - g) * hv.x;
                acc1[mt][nt][2 * p + 0] = v; rsum[mt][p] += v; rsq[mt][p] += v * v;
                pre = acc2[mt][nt][2 * p + 1] + sc[256 + cb + 1];
                g = 1.f / (1.f + expf(-pre));
                v = g * acc1[mt][nt][2 * p + 1] + (1.f - g) * hv.y;
                acc1[mt][nt][2 * p + 1] = v; rsum[mt][p] += v; rsq[mt][p] += v * v;
            }
        }
    }
    // quad reduce (covers this warp's 64-col half), then exchange halves via smem
#pragma unroll
    for (int mt = 0; mt < 2; mt++) {
#pragma unroll
        for (int p = 0; p < 2; p++) {
            rsum[mt][p] += __shfl_xor_sync(0xffffffffu, rsum[mt][p], 1);
            rsum[mt][p] += __shfl_xor_sync(0xffffffffu, rsum[mt][p], 2);
            rsq[mt][p] += __shfl_xor_sync(0xffffffffu, rsq[mt][p], 1);
            rsq[mt][p] += __shfl_xor_sync(0xffffffffu, rsq[mt][p], 2);
        }
    }
    if (tq == 0) {
#pragma unroll
        for (int mt = 0; mt < 2; mt++)
#pragma unroll
            for (int p = 0; p < 2; p++) {
                int lrow = warpM * 32 + mt * 16 + p * 8 + gid;
                lnb[lrow * 4 + warpN * 2 + 0] = rsum[mt][p];
                lnb[lrow * 4 + warpN * 2 + 1] = rsq[mt][p];
            }
    }
    __syncthreads();
#pragma unroll
    for (int mt = 0; mt < 2; mt++) {
#pragma unroll
        for (int p = 0; p < 2; p++) {
            int lrow = warpM * 32 + mt * 16 + p * 8 + gid;
            int row = r0 + lrow;
            if (row >= n) continue;
            float sum = lnb[lrow * 4 + 0] + lnb[lrow * 4 + 2];
            float sq  = lnb[lrow * 4 + 1] + lnb[lrow * 4 + 3];
            float mu = sum * (1.f / 128.f);
            float var = sq * (1.f / 128.f) - mu * mu;
            float rs = rsqrtf(var + 1e-5f);
            float* orow = Hout + (size_t)row * H;
#pragma unroll
            for (int nt = 0; nt < 8; nt++) {
                int cb = warpN * 64 + nt * 8 + 2 * tq;
                float2 o;
                o.x = fmaxf(fmaf((acc1[mt][nt][2 * p + 0] - mu) * rs, sc[384 + cb], sc[512 + cb]), 0.f);
                o.y = fmaxf(fmaf((acc1[mt][nt][2 * p + 1] - mu) * rs, sc[384 + cb + 1], sc[512 + cb + 1]), 0.f);
                *(float2*)(orow + cb) = o;
            }
        }
    }
}

// ---------------- graph prep ----------------
__global__ void zero_kernel(int n) {
    int i = blockIdx.x * blockDim.x + threadIdx.x;
    if (i < n) { g_indeg[i] = 0; g_outdeg[i] = 0; g_cursor[i] = 0; }
    if (i == 0) g_maxbits = encf(neg_inf());
}
__global__ void deg_kernel(const int* __restrict__ src, const int* __restrict__ dst, int e) {
    int i = blockIdx.x * blockDim.x + threadIdx.x;
    if (i < e) { atomicAdd(&g_indeg[dst[i]], 1); atomicAdd(&g_outdeg[src[i]], 1); }
}
__global__ void prep_kernel(int n) {
    int i = blockIdx.x * blockDim.x + threadIdx.x;
    if (i < n) {
        int d = g_indeg[i];
        g_hp[i] = d > 0 ? 1.f : 0.f;
        g_invdeg[i] = 1.f / (float)(d > 0 ? d : 1);
    }
}
__global__ void scan1_kernel(int n) {
    __shared__ int sm[1024];
    int t = threadIdx.x;
    int i = blockIdx.x * 1024 + t;
    int v = (i < n) ? g_indeg[i] : 0;
    sm[t] = v;
    __syncthreads();
    for (int off = 1; off < 1024; off <<= 1) {
        int x = (t >= off) ? sm[t - off] : 0;
        __syncthreads();
        sm[t] += x;
        __syncthreads();
    }
    if (i < n) g_off[i] = sm[t] - v;
    if (t == 1023) g_bsum[blockIdx.x] = sm[1023];
}
__global__ void scan2_kernel(int nb) {
    if (threadIdx.x == 0) {
        int c = 0;
        for (int i = 0; i < nb; i++) { int x = g_bsum[i]; g_bsum[i] = c; c += x; }
    }
}
__global__ void scan3_kernel(int n) {
    int i = blockIdx.x * blockDim.x + threadIdx.x;
    if (i < n) g_off[i] += g_bsum[i >> 10];
}
__global__ void fill_kernel(const int* __restrict__ src, const int* __restrict__ dst, int e) {
    int i = blockIdx.x * blockDim.x + threadIdx.x;
    if (i < e) {
        int d = dst[i];
        int p = g_off[d] + atomicAdd(&g_cursor[d], 1);
        g_csr[p] = src[i];
    }
}

// ---------------- neighbor mean ----------------
__global__ void neigh_kernel(const float* __restrict__ Hin, float* __restrict__ Ng, int n) {
    int gw = (blockIdx.x * blockDim.x + threadIdx.x) >> 5;
    int lane = threadIdx.x & 31;
    if (gw >= n) return;
    int start = g_off[gw];
    int deg = g_indeg[gw];
    float4 acc = make_float4(0.f, 0.f, 0.f, 0.f);
    const float4* H4 = (const float4*)Hin;
    for (int base = 0; base < deg; base += 32) {
        int e = base + lane;
        int s = (e < deg) ? g_csr[start + e] : 0;
        int cnt = min(32, deg - base);
        for (int j = 0; j < cnt; j++) {
            int sj = __shfl_sync(0xffffffffu, s, j);
            float4 hv = H4[(size_t)sj * 32 + lane];
            acc.x += hv.x; acc.y += hv.y; acc.z += hv.z; acc.w += hv.w;
        }
    }
    float iv = g_invdeg[gw];
    acc.x *= iv; acc.y *= iv; acc.z *= iv; acc.w *= iv;
    ((float4*)Ng)[(size_t)gw * 32 + lane] = acc;
}

// ---------------- pooling ----------------
__global__ void score_kernel(const float* __restrict__ Ab, const float* __restrict__ Wsc,
                             const float* __restrict__ bsc, int n) {
    int gw = (blockIdx.x * blockDim.x + threadIdx.x) >> 5;
    int lane = threadIdx.x & 31;
    if (gw >= n) return;
    float4 av = ((const float4*)Ab)[(size_t)gw * 32 + lane];
    float4 wv = ((const float4*)Wsc)[lane];
    float p = av.x * wv.x + av.y * wv.y + av.z * wv.z + av.w * wv.w;
#pragma unroll
    for (int m = 16; m >= 1; m >>= 1) p += __shfl_xor_sync(0xffffffffu, p, m);
    if (lane == 0) {
        bool sink = (g_outdeg[gw] == 0);
        float sc = p + bsc[0];
        g_scores[gw] = sink ? sc : neg_inf();
        if (sink) atomicMax(&g_maxbits, encf(sc));
    }
}
__global__ void pool_kernel(const float* __restrict__ Hin, float* __restrict__ gout, int n) {
    __shared__ float sred[1024];
    __shared__ float sg[H];
    int tid = threadIdx.x;
    float mx = decf(g_maxbits);
    float local = 0.f;
    for (int i = tid; i < n; i += 1024) {
        float s = g_scores[i];
        if (s >= -1e30f) local += expf(s - mx);
    }
    sred[tid] = local;
    if (tid < H) sg[tid] = 0.f;
    __syncthreads();
    for (int s = 512; s > 0; s >>= 1) {
        if (tid < s) sred[tid] += sred[tid + s];
        __syncthreads();
    }
    float inv = 1.f / sred[0];
    for (int i = tid; i < n; i += 1024) {
        float s = g_scores[i];
        if (s >= -1e30f) {
            float w = expf(s - mx) * inv;
            const float* hr = Hin + (size_t)i * H;
            for (int c = 0; c < H; c++) atomicAdd(&sg[c], w * hr[c]);
        }
    }
    __syncthreads();
    if (tid < H) gout[tid] = sg[tid];
}

// ---------------- launch ----------------
extern "C" void kernel_launch(void* const* d_in, const int* in_sizes, int n_in,
                              void* d_out, int out_size)
{
    const float* node_feats = (const float*)d_in[0];
    const int*   src        = (const int*)d_in[1];
    const int*   dst        = (const int*)d_in[2];
    const float* W_in       = (const float*)d_in[3];
    const float* b_in       = (const float*)d_in[4];
    const float* Ws         = (const float*)d_in[5];
    const float* bs         = (const float*)d_in[6];
    const float* Wn         = (const float*)d_in[7];
    const float* bn         = (const float*)d_in[8];
    const float* Wg         = (const float*)d_in[9];
    const float* bg         = (const float*)d_in[10];
    const float* gamma      = (const float*)d_in[11];
    const float* beta       = (const float*)d_in[12];
    const float* W_att      = (const float*)d_in[13];
    const float* b_att      = (const float*)d_in[14];
    const float* W_score    = (const float*)d_in[15];
    const float* b_score    = (const float*)d_in[16];

    int n = in_sizes[0] / H;
    int e = in_sizes[1];
    int L = in_sizes[6] / H;

    float* out_h = (float*)d_out;
    float* out_g = out_h + (size_t)n * H;

    float *hA, *hB, *neigh, *mbuf, *hp;
    cudaGetSymbolAddress((void**)&hA, g_hA);
    cudaGetSymbolAddress((void**)&hB, g_hB);
    cudaGetSymbolAddress((void**)&neigh, g_neigh);
    cudaGetSymbolAddress((void**)&mbuf, g_m);
    cudaGetSymbolAddress((void**)&hp, g_hp);

    cudaFuncSetAttribute(tc_gemm<0>, cudaFuncAttributeMaxDynamicSharedMemorySize, SMEM_BYTES);
    cudaFuncSetAttribute(tc_gemm<2>, cudaFuncAttributeMaxDynamicSharedMemorySize, SMEM_BYTES);
    cudaFuncSetAttribute(tc_layer,   cudaFuncAttributeMaxDynamicSharedMemorySize, LSMEM_BYTES);

    int nbN = (n + 255) / 256;
    int nbE = (e + 255) / 256;
    int nbT = (n + 127) / 128;
    int nbW = (n + 7) / 8;
    int nbS = (n + 1023) / 1024;

    // graph prep
    zero_kernel<<<nbN, 256>>>(n);
    deg_kernel<<<nbE, 256>>>(src, dst, e);
    prep_kernel<<<nbN, 256>>>(n);
    scan1_kernel<<<nbS, 1024>>>(n);
    scan2_kernel<<<1, 32>>>(nbS);
    scan3_kernel<<<nbN, 256>>>(n);
    fill_kernel<<<nbE, 256>>>(src, dst, e);

    // input projection
    tc_gemm<0><<<nbT, 256, SMEM_BYTES>>>(node_feats, W_in, b_in, hA, n);

    float* cur = hA;
    float* other = hB;
    for (int i = 0; i < L; i++) {
        const float* Ws_i = Ws + (size_t)i * H * H;
        const float* bs_i = bs + (size_t)i * H;
        const float* Wn_i = Wn + (size_t)i * H * H;
        const float* bn_i = bn + (size_t)i * H;
        const float* WgA  = Wg + (size_t)i * 2 * H * H;   // multiplies h
        const float* WgB  = WgA + (size_t)H * H;          // multiplies m
        const float* bg_i = bg + (size_t)i * H;
        const float* ga_i = gamma + (size_t)i * H;
        const float* be_i = beta + (size_t)i * H;

        neigh_kernel<<<nbW, 256>>>(cur, neigh, n);
        float* outp = (i == L - 1) ? out_h : other;
        tc_layer<<<nbT, 256, LSMEM_BYTES>>>(cur, neigh, Ws_i, bs_i, Wn_i, bn_i,
                                            WgA, WgB, bg_i, hp, ga_i, be_i, outp, n);
        other = cur;
        cur = outp;
    }

    // attention pooling over sinks
    tc_gemm<2><<<nbT, 256, SMEM_BYTES>>>(cur, W_att, b_att, mbuf, n);
    score_kernel<<<nbW, 256>>>(mbuf, W_score, b_score, n);
    pool_kernel<<<1, 1024>>>(cur, out_g, n);
}

// round 6
// speedup vs baseline: 2.9642x; 1.3958x over previous
#include <cuda_runtime.h>
#include <cuda_fp16.h>
#include <math.h>
#include <stdint.h>

#define MAXN 100000
#define MAXE 800000
#define H 128

// ---------------- device scratch ----------------
__device__ float g_hA[(size_t)MAXN * H];
__device__ float g_hB[(size_t)MAXN * H];
__device__ float g_neigh[(size_t)MAXN * H];
__device__ int   g_indeg[MAXN];
__device__ int   g_outdeg[MAXN];
__device__ int   g_cursor[MAXN];
__device__ int   g_off[MAXN];
__device__ int   g_csr[MAXE];
__device__ int   g_bsum[128];
__device__ float g_hp[MAXN];
__device__ float g_invdeg[MAXN];
__device__ float g_scores[MAXN];
__device__ float g_emb[H];
__device__ float g_sumexp;
__device__ unsigned g_maxbits;

__device__ __forceinline__ float neg_inf() { return __int_as_float(0xff800000); }
__device__ __forceinline__ unsigned encf(float f) {
    unsigned u = __float_as_uint(f);
    return (u & 0x80000000u) ? ~u : (u | 0x80000000u);
}
__device__ __forceinline__ float decf(unsigned u) {
    return (u & 0x80000000u) ? __uint_as_float(u ^ 0x80000000u) : __uint_as_float(~u);
}

// ---------------- fp16 mma.sync helpers ----------------
__device__ __forceinline__ uint32_t f2h2(float a, float b) {
    __half2 h = __floats2half2_rn(a, b);
    return *(uint32_t*)&h;
}
__device__ __forceinline__ void mma16816(float* c, uint32_t a0, uint32_t a1, uint32_t a2, uint32_t a3,
                                         uint32_t b0, uint32_t b1) {
    asm volatile("mma.sync.aligned.m16n8k16.row.col.f32.f16.f16.f32 "
                 "{%0,%1,%2,%3}, {%4,%5,%6,%7}, {%8,%9}, {%0,%1,%2,%3};"
                 : "+f"(c[0]), "+f"(c[1]), "+f"(c[2]), "+f"(c[3])
                 : "r"(a0), "r"(a1), "r"(a2), "r"(a3), "r"(b0), "r"(b1));
}

// A tile: 128 rows x 64 half2 (k-pairs), stride 68 u32.  W tile: 64 kpair-rows x 128 half2, stride 136 u32.
#define AP_STRIDE 68
#define WP_STRIDE 136
#define SZ_AP (128 * AP_STRIDE)
#define SZ_WP (64 * WP_STRIDE)
#define GSMEM_BYTES ((SZ_AP + SZ_WP + 128) * 4)
#define SSMEM_BYTES ((SZ_AP + SZ_WP + 512) * 4)
#define LSMEM_BYTES ((2 * SZ_AP + SZ_WP + 640 + 512) * 4)

// load 128x128 f32 rows [r0, r0+128) as half2 k-pairs
__device__ __forceinline__ void load_tile_a(const float4* __restrict__ G, int r0, int n, uint32_t* sm) {
    int t = threadIdx.x;
#pragma unroll
    for (int i = 0; i < 16; i++) {
        int g = t + i * 256;
        int row = g >> 5, c4 = g & 31;
        float4 v = make_float4(0.f, 0.f, 0.f, 0.f);
        if (r0 + row < n) v = G[(size_t)(r0 + row) * 32 + c4];
        uint2 w;
        w.x = f2h2(v.x, v.y);
        w.y = f2h2(v.z, v.w);
        *(uint2*)(sm + row * AP_STRIDE + c4 * 2) = w;
    }
}
// load 128x128 weight [k][n] as half2 pairs over k: WP[kp][n] = {W[2kp][n], W[2kp+1][n]}
__device__ __forceinline__ void load_tile_w(const float4* __restrict__ G, uint32_t* sm) {
    int t = threadIdx.x;
#pragma unroll
    for (int i = 0; i < 8; i++) {
        int g = t + i * 256;
        int kp = g >> 5, c4 = g & 31;
        float4 v0 = G[(size_t)(2 * kp) * 32 + c4];
        float4 v1 = G[(size_t)(2 * kp + 1) * 32 + c4];
        uint4 w;
        w.x = f2h2(v0.x, v1.x);
        w.y = f2h2(v0.y, v1.y);
        w.z = f2h2(v0.z, v1.z);
        w.w = f2h2(v0.w, v1.w);
        *(uint4*)(sm + kp * WP_STRIDE + c4 * 4) = w;
    }
}

// warp-tile MMA (2Mx8N fragments per warp), K=128 in 8 steps of 16
__device__ __forceinline__ void mma_tile(const uint32_t* AP, const uint32_t* WP,
                                         float acc[2][8][4], int warpM, int warpN,
                                         int gid, int tq) {
#pragma unroll
    for (int ks = 0; ks < 8; ks++) {
        int kp0 = ks * 8;
        uint32_t a[2][4];
#pragma unroll
        for (int mt = 0; mt < 2; mt++) {
            int rb = warpM * 32 + mt * 16;
            a[mt][0] = AP[(rb + gid) * AP_STRIDE + kp0 + tq];
            a[mt][1] = AP[(rb + gid + 8) * AP_STRIDE + kp0 + tq];
            a[mt][2] = AP[(rb + gid) * AP_STRIDE + kp0 + tq + 4];
            a[mt][3] = AP[(rb + gid + 8) * AP_STRIDE + kp0 + tq + 4];
        }
#pragma unroll
        for (int nt = 0; nt < 8; nt++) {
            int cb = warpN * 64 + nt * 8 + gid;
            uint32_t b0 = WP[(kp0 + tq) * WP_STRIDE + cb];
            uint32_t b1 = WP[(kp0 + tq + 4) * WP_STRIDE + cb];
#pragma unroll
            for (int mt = 0; mt < 2; mt++) mma16816(acc[mt][nt], a[mt][0], a[mt][1], a[mt][2], a[mt][3], b0, b1);
        }
    }
}

// ---------------- GEMM: C = A@W + bias ----------------
__global__ __launch_bounds__(256) void tc_gemm(
    const float* __restrict__ A, const float* __restrict__ W,
    const float* __restrict__ bias, float* __restrict__ C, int n)
{
    extern __shared__ uint32_t smem[];
    uint32_t* AP = smem;
    uint32_t* WP = smem + SZ_AP;
    float* sb = (float*)(smem + SZ_AP + SZ_WP);

    int tid = threadIdx.x, wid = tid >> 5, lane = tid & 31;
    int warpM = wid >> 1, warpN = wid & 1, gid = lane >> 2, tq = lane & 3;
    int r0 = blockIdx.x * 128;

    load_tile_a((const float4*)A, r0, n, AP);
    load_tile_w((const float4*)W, WP);
    if (tid < 128) sb[tid] = bias[tid];
    __syncthreads();

    float acc[2][8][4];
#pragma unroll
    for (int mt = 0; mt < 2; mt++)
#pragma unroll
        for (int nt = 0; nt < 8; nt++)
#pragma unroll
            for (int j = 0; j < 4; j++) acc[mt][nt][j] = 0.f;

    mma_tile(AP, WP, acc, warpM, warpN, gid, tq);

#pragma unroll
    for (int mt = 0; mt < 2; mt++) {
#pragma unroll
        for (int nt = 0; nt < 8; nt++) {
            int cb = warpN * 64 + nt * 8 + 2 * tq;
            float bx = sb[cb], by = sb[cb + 1];
#pragma unroll
            for (int p = 0; p < 2; p++) {
                int row = r0 + warpM * 32 + mt * 16 + p * 8 + gid;
                if (row < n) {
                    float2 o;
                    o.x = acc[mt][nt][2 * p + 0] + bx;
                    o.y = acc[mt][nt][2 * p + 1] + by;
                    *(float2*)(C + (size_t)row * H + cb) = o;
                }
            }
        }
    }
}

// ---------------- fused layer kernel ----------------
__global__ __launch_bounds__(256) void tc_layer(
    const float* __restrict__ cur, const float* __restrict__ neighb,
    const float* __restrict__ Ws, const float* __restrict__ bs,
    const float* __restrict__ Wn, const float* __restrict__ bn,
    const float* __restrict__ WgA, const float* __restrict__ WgB, const float* __restrict__ bg,
    const float* __restrict__ coef,
    const float* __restrict__ gamma, const float* __restrict__ beta,
    float* __restrict__ Hout, int n)
{
    extern __shared__ uint32_t smem[];
    uint32_t* Acur = smem;                        // cur tile (fp16 pairs)
    uint32_t* WP   = smem + SZ_AP;                // weight panel (swapped per stage)
    uint32_t* Am   = smem + SZ_AP + SZ_WP;        // neigh tile, later m tile
    float* sc  = (float*)(smem + 2 * SZ_AP + SZ_WP); // bs|bn|bg|gamma|beta
    float* lnb = sc + 640;

    int tid = threadIdx.x, wid = tid >> 5, lane = tid & 31;
    int warpM = wid >> 1, warpN = wid & 1, gid = lane >> 2, tq = lane & 3;
    int r0 = blockIdx.x * 128;

    load_tile_a((const float4*)cur, r0, n, Acur);
    load_tile_a((const float4*)neighb, r0, n, Am);
    load_tile_w((const float4*)Ws, WP);
    if (tid < 128) { sc[tid] = bs[tid]; sc[128 + tid] = bn[tid]; }
    else { int t = tid - 128; sc[256 + t] = bg[t]; sc[384 + t] = gamma[t]; sc[512 + t] = beta[t]; }
    __syncthreads();

    float acc1[2][8][4];
#pragma unroll
    for (int mt = 0; mt < 2; mt++)
#pragma unroll
        for (int nt = 0; nt < 8; nt++)
#pragma unroll
            for (int j = 0; j < 4; j++) acc1[mt][nt][j] = 0.f;

    mma_tile(Acur, WP, acc1, warpM, warpN, gid, tq);       // stage 1: cur@Ws
    __syncthreads();
    load_tile_w((const float4*)Wn, WP);
    __syncthreads();
    mma_tile(Am, WP, acc1, warpM, warpN, gid, tq);         // stage 2: += neigh@Wn
    __syncthreads();

    // m = acc1 + bs + cf*bn (exact fp32 in regs); write fp16 m over Am
#pragma unroll
    for (int mt = 0; mt < 2; mt++) {
#pragma unroll
        for (int p = 0; p < 2; p++) {
            int lrow = warpM * 32 + mt * 16 + p * 8 + gid;
            int row = r0 + lrow;
            if (row >= n) continue;
            float cf = coef[row];
#pragma unroll
            for (int nt = 0; nt < 8; nt++) {
                int cb = warpN * 64 + nt * 8 + 2 * tq;
                float v0 = acc1[mt][nt][2 * p + 0] + sc[cb + 0] + cf * sc[128 + cb + 0];
                float v1 = acc1[mt][nt][2 * p + 1] + sc[cb + 1] + cf * sc[128 + cb + 1];
                acc1[mt][nt][2 * p + 0] = v0;
                acc1[mt][nt][2 * p + 1] = v1;
                Am[lrow * AP_STRIDE + (cb >> 1)] = f2h2(v0, v1);
            }
        }
    }
    load_tile_w((const float4*)WgA, WP);
    __syncthreads();

    float acc2[2][8][4];
#pragma unroll
    for (int mt = 0; mt < 2; mt++)
#pragma unroll
        for (int nt = 0; nt < 8; nt++)
#pragma unroll
            for (int j = 0; j < 4; j++) acc2[mt][nt][j] = 0.f;

    mma_tile(Acur, WP, acc2, warpM, warpN, gid, tq);       // stage 3: cur@WgA
    __syncthreads();
    load_tile_w((const float4*)WgB, WP);
    __syncthreads();
    mma_tile(Am, WP, acc2, warpM, warpN, gid, tq);         // stage 4: += m@WgB

    // epilogue: gate + blend + LN + ReLU
    float rsum[2][2] = {{0.f, 0.f}, {0.f, 0.f}};
    float rsq[2][2] = {{0.f, 0.f}, {0.f, 0.f}};
#pragma unroll
    for (int mt = 0; mt < 2; mt++) {
#pragma unroll
        for (int p = 0; p < 2; p++) {
            int row = r0 + warpM * 32 + mt * 16 + p * 8 + gid;
            if (row >= n) continue;
            const float* hrow = cur + (size_t)row * H;
#pragma unroll
            for (int nt = 0; nt < 8; nt++) {
                int cb = warpN * 64 + nt * 8 + 2 * tq;
                float2 hv = *(const float2*)(hrow + cb);
                float pre, g, v;
                pre = acc2[mt][nt][2 * p + 0] + sc[256 + cb];
                g = 1.f / (1.f + expf(-pre));
                v = g * acc1[mt][nt][2 * p + 0] + (1.f - g) * hv.x;
                acc1[mt][nt][2 * p + 0] = v; rsum[mt][p] += v; rsq[mt][p] += v * v;
                pre = acc2[mt][nt][2 * p + 1] + sc[256 + cb + 1];
                g = 1.f / (1.f + expf(-pre));
                v = g * acc1[mt][nt][2 * p + 1] + (1.f - g) * hv.y;
                acc1[mt][nt][2 * p + 1] = v; rsum[mt][p] += v; rsq[mt][p] += v * v;
            }
        }
    }
#pragma unroll
    for (int mt = 0; mt < 2; mt++) {
#pragma unroll
        for (int p = 0; p < 2; p++) {
            rsum[mt][p] += __shfl_xor_sync(0xffffffffu, rsum[mt][p], 1);
            rsum[mt][p] += __shfl_xor_sync(0xffffffffu, rsum[mt][p], 2);
            rsq[mt][p] += __shfl_xor_sync(0xffffffffu, rsq[mt][p], 1);
            rsq[mt][p] += __shfl_xor_sync(0xffffffffu, rsq[mt][p], 2);
        }
    }
    if (tq == 0) {
#pragma unroll
        for (int mt = 0; mt < 2; mt++)
#pragma unroll
            for (int p = 0; p < 2; p++) {
                int lrow = warpM * 32 + mt * 16 + p * 8 + gid;
                lnb[lrow * 4 + warpN * 2 + 0] = rsum[mt][p];
                lnb[lrow * 4 + warpN * 2 + 1] = rsq[mt][p];
            }
    }
    __syncthreads();
#pragma unroll
    for (int mt = 0; mt < 2; mt++) {
#pragma unroll
        for (int p = 0; p < 2; p++) {
            int lrow = warpM * 32 + mt * 16 + p * 8 + gid;
            int row = r0 + lrow;
            if (row >= n) continue;
            float sum = lnb[lrow * 4 + 0] + lnb[lrow * 4 + 2];
            float sq  = lnb[lrow * 4 + 1] + lnb[lrow * 4 + 3];
            float mu = sum * (1.f / 128.f);
            float var = sq * (1.f / 128.f) - mu * mu;
            float rs = rsqrtf(var + 1e-5f);
            float* orow = Hout + (size_t)row * H;
#pragma unroll
            for (int nt = 0; nt < 8; nt++) {
                int cb = warpN * 64 + nt * 8 + 2 * tq;
                float2 o;
                o.x = fmaxf(fmaf((acc1[mt][nt][2 * p + 0] - mu) * rs, sc[384 + cb], sc[512 + cb]), 0.f);
                o.y = fmaxf(fmaf((acc1[mt][nt][2 * p + 1] - mu) * rs, sc[384 + cb + 1], sc[512 + cb + 1]), 0.f);
                *(float2*)(orow + cb) = o;
            }
        }
    }
}

// ---------------- fused attention score: a=tanh(h@W_att+b); score=a.Wsc+bsc ----------------
__global__ __launch_bounds__(256) void tc_score(
    const float* __restrict__ A, const float* __restrict__ W,
    const float* __restrict__ bias, const float* __restrict__ Wsc,
    const float* __restrict__ bsc, int n)
{
    extern __shared__ uint32_t smem[];
    uint32_t* AP = smem;
    uint32_t* WP = smem + SZ_AP;
    float* sb = (float*)(smem + SZ_AP + SZ_WP);
    float* sw = sb + 128;
    float* lnb = sw + 128;

    int tid = threadIdx.x, wid = tid >> 5, lane = tid & 31;
    int warpM = wid >> 1, warpN = wid & 1, gid = lane >> 2, tq = lane & 3;
    int r0 = blockIdx.x * 128;

    load_tile_a((const float4*)A, r0, n, AP);
    load_tile_w((const float4*)W, WP);
    if (tid < 128) sb[tid] = bias[tid];
    else sw[tid - 128] = Wsc[tid - 128];
    __syncthreads();

    float acc[2][8][4];
#pragma unroll
    for (int mt = 0; mt < 2; mt++)
#pragma unroll
        for (int nt = 0; nt < 8; nt++)
#pragma unroll
            for (int j = 0; j < 4; j++) acc[mt][nt][j] = 0.f;

    mma_tile(AP, WP, acc, warpM, warpN, gid, tq);

    float part[2][2] = {{0.f, 0.f}, {0.f, 0.f}};
#pragma unroll
    for (int mt = 0; mt < 2; mt++)
#pragma unroll
        for (int nt = 0; nt < 8; nt++) {
            int cb = warpN * 64 + nt * 8 + 2 * tq;
#pragma unroll
            for (int p = 0; p < 2; p++) {
                part[mt][p] += tanhf(acc[mt][nt][2 * p + 0] + sb[cb]) * sw[cb];
                part[mt][p] += tanhf(acc[mt][nt][2 * p + 1] + sb[cb + 1]) * sw[cb + 1];
            }
        }
#pragma unroll
    for (int mt = 0; mt < 2; mt++)
#pragma unroll
        for (int p = 0; p < 2; p++) {
            part[mt][p] += __shfl_xor_sync(0xffffffffu, part[mt][p], 1);
            part[mt][p] += __shfl_xor_sync(0xffffffffu, part[mt][p], 2);
        }
    if (tq == 0) {
#pragma unroll
        for (int mt = 0; mt < 2; mt++)
#pragma unroll
            for (int p = 0; p < 2; p++) {
                int lrow = warpM * 32 + mt * 16 + p * 8 + gid;
                lnb[lrow * 2 + warpN] = part[mt][p];
            }
    }
    __syncthreads();
    if (warpN == 0 && tq == 0) {
#pragma unroll
        for (int mt = 0; mt < 2; mt++)
#pragma unroll
            for (int p = 0; p < 2; p++) {
                int lrow = warpM * 32 + mt * 16 + p * 8 + gid;
                int row = r0 + lrow;
                if (row >= n) continue;
                float scv = lnb[lrow * 2 + 0] + lnb[lrow * 2 + 1] + bsc[0];
                bool sink = (g_outdeg[row] == 0);
                g_scores[row] = sink ? scv : neg_inf();
                if (sink) atomicMax(&g_maxbits, encf(scv));
            }
    }
}

// ---------------- graph prep ----------------
__global__ void zero_kernel(int n) {
    int i = blockIdx.x * blockDim.x + threadIdx.x;
    if (i < n) { g_indeg[i] = 0; g_outdeg[i] = 0; g_cursor[i] = 0; }
    if (i < H) g_emb[i] = 0.f;
    if (i == 0) { g_maxbits = encf(neg_inf()); g_sumexp = 0.f; }
}
__global__ void deg_kernel(const int* __restrict__ src, const int* __restrict__ dst, int e) {
    int i = blockIdx.x * blockDim.x + threadIdx.x;
    if (i < e) { atomicAdd(&g_indeg[dst[i]], 1); atomicAdd(&g_outdeg[src[i]], 1); }
}
__global__ void prep_kernel(int n) {
    int i = blockIdx.x * blockDim.x + threadIdx.x;
    if (i < n) {
        int d = g_indeg[i];
        g_hp[i] = d > 0 ? 1.f : 0.f;
        g_invdeg[i] = 1.f / (float)(d > 0 ? d : 1);
    }
}
__global__ void scan1_kernel(int n) {
    __shared__ int sm[1024];
    int t = threadIdx.x;
    int i = blockIdx.x * 1024 + t;
    int v = (i < n) ? g_indeg[i] : 0;
    sm[t] = v;
    __syncthreads();
    for (int off = 1; off < 1024; off <<= 1) {
        int x = (t >= off) ? sm[t - off] : 0;
        __syncthreads();
        sm[t] += x;
        __syncthreads();
    }
    if (i < n) g_off[i] = sm[t] - v;
    if (t == 1023) g_bsum[blockIdx.x] = sm[1023];
}
__global__ void scan2_kernel(int nb) {
    if (threadIdx.x == 0) {
        int c = 0;
        for (int i = 0; i < nb; i++) { int x = g_bsum[i]; g_bsum[i] = c; c += x; }
    }
}
__global__ void scan3_kernel(int n) {
    int i = blockIdx.x * blockDim.x + threadIdx.x;
    if (i < n) g_off[i] += g_bsum[i >> 10];
}
__global__ void fill_kernel(const int* __restrict__ src, const int* __restrict__ dst, int e) {
    int i = blockIdx.x * blockDim.x + threadIdx.x;
    if (i < e) {
        int d = dst[i];
        int p = g_off[d] + atomicAdd(&g_cursor[d], 1);
        g_csr[p] = src[i];
    }
}

// ---------------- neighbor mean ----------------
__global__ void neigh_kernel(const float* __restrict__ Hin, float* __restrict__ Ng, int n) {
    int gw = (blockIdx.x * blockDim.x + threadIdx.x) >> 5;
    int lane = threadIdx.x & 31;
    if (gw >= n) return;
    int start = g_off[gw];
    int deg = g_indeg[gw];
    float4 acc = make_float4(0.f, 0.f, 0.f, 0.f);
    const float4* H4 = (const float4*)Hin;
    for (int base = 0; base < deg; base += 32) {
        int e = base + lane;
        int s = (e < deg) ? g_csr[start + e] : 0;
        int cnt = min(32, deg - base);
        for (int j = 0; j < cnt; j++) {
            int sj = __shfl_sync(0xffffffffu, s, j);
            float4 hv = H4[(size_t)sj * 32 + lane];
            acc.x += hv.x; acc.y += hv.y; acc.z += hv.z; acc.w += hv.w;
        }
    }
    float iv = g_invdeg[gw];
    acc.x *= iv; acc.y *= iv; acc.z *= iv; acc.w *= iv;
    ((float4*)Ng)[(size_t)gw * 32 + lane] = acc;
}

// ---------------- pooling (multi-block): numerator/denominator accumulation ----------------
__global__ void pool2_kernel(const float* __restrict__ Hin, int n) {
    __shared__ float sb[8 * 128];
    __shared__ float se[8];
    int tid = threadIdx.x, w = tid >> 5, lane = tid & 31;
    int gw = (blockIdx.x * blockDim.x + tid) >> 5;
    int nw = (gridDim.x * blockDim.x) >> 5;
    float mx = decf(g_maxbits);
    const float4* H4 = (const float4*)Hin;
    float4 acc = make_float4(0.f, 0.f, 0.f, 0.f);
    float es = 0.f;
    for (int i = gw; i < n; i += nw) {
        float s = g_scores[i];
        if (s >= -1e30f) {
            float e = expf(s - mx);
            if (lane == 0) es += e;
            float4 hv = H4[(size_t)i * 32 + lane];
            acc.x += e * hv.x; acc.y += e * hv.y; acc.z += e * hv.z; acc.w += e * hv.w;
        }
    }
    *(float4*)&sb[w * 128 + lane * 4] = acc;
    if (lane == 0) se[w] = es;
    __syncthreads();
    if (tid < 128) {
        float t = 0.f;
#pragma unroll
        for (int j = 0; j < 8; j++) t += sb[j * 128 + tid];
        if (t != 0.f) atomicAdd(&g_emb[tid], t);
    }
    if (tid == 0) {
        float t = 0.f;
#pragma unroll
        for (int j = 0; j < 8; j++) t += se[j];
        if (t != 0.f) atomicAdd(&g_sumexp, t);
    }
}
__global__ void finish_kernel(float* __restrict__ gout) {
    int t = threadIdx.x;
    gout[t] = g_emb[t] / g_sumexp;
}

// ---------------- launch ----------------
extern "C" void kernel_launch(void* const* d_in, const int* in_sizes, int n_in,
                              void* d_out, int out_size)
{
    const float* node_feats = (const float*)d_in[0];
    const int*   src        = (const int*)d_in[1];
    const int*   dst        = (const int*)d_in[2];
    const float* W_in       = (const float*)d_in[3];
    const float* b_in       = (const float*)d_in[4];
    const float* Ws         = (const float*)d_in[5];
    const float* bs         = (const float*)d_in[6];
    const float* Wn         = (const float*)d_in[7];
    const float* bn         = (const float*)d_in[8];
    const float* Wg         = (const float*)d_in[9];
    const float* bg         = (const float*)d_in[10];
    const float* gamma      = (const float*)d_in[11];
    const float* beta       = (const float*)d_in[12];
    const float* W_att      = (const float*)d_in[13];
    const float* b_att      = (const float*)d_in[14];
    const float* W_score    = (const float*)d_in[15];
    const float* b_score    = (const float*)d_in[16];

    int n = in_sizes[0] / H;
    int e = in_sizes[1];
    int L = in_sizes[6] / H;

    float* out_h = (float*)d_out;
    float* out_g = out_h + (size_t)n * H;

    float *hA, *hB, *neigh, *hp;
    cudaGetSymbolAddress((void**)&hA, g_hA);
    cudaGetSymbolAddress((void**)&hB, g_hB);
    cudaGetSymbolAddress((void**)&neigh, g_neigh);
    cudaGetSymbolAddress((void**)&hp, g_hp);

    cudaFuncSetAttribute(tc_gemm,  cudaFuncAttributeMaxDynamicSharedMemorySize, GSMEM_BYTES);
    cudaFuncSetAttribute(tc_score, cudaFuncAttributeMaxDynamicSharedMemorySize, SSMEM_BYTES);
    cudaFuncSetAttribute(tc_layer, cudaFuncAttributeMaxDynamicSharedMemorySize, LSMEM_BYTES);

    int nbN = (n + 255) / 256;
    int nbE = (e + 255) / 256;
    int nbT = (n + 127) / 128;
    int nbW = (n + 7) / 8;
    int nbS = (n + 1023) / 1024;

    // graph prep
    zero_kernel<<<nbN, 256>>>(n);
    deg_kernel<<<nbE, 256>>>(src, dst, e);
    prep_kernel<<<nbN, 256>>>(n);
    scan1_kernel<<<nbS, 1024>>>(n);
    scan2_kernel<<<1, 32>>>(nbS);
    scan3_kernel<<<nbN, 256>>>(n);
    fill_kernel<<<nbE, 256>>>(src, dst, e);

    // input projection
    tc_gemm<<<nbT, 256, GSMEM_BYTES>>>(node_feats, W_in, b_in, hA, n);

    float* cur = hA;
    float* other = hB;
    for (int i = 0; i < L; i++) {
        const float* Ws_i = Ws + (size_t)i * H * H;
        const float* bs_i = bs + (size_t)i * H;
        const float* Wn_i = Wn + (size_t)i * H * H;
        const float* bn_i = bn + (size_t)i * H;
        const float* WgA  = Wg + (size_t)i * 2 * H * H;   // multiplies h
        const float* WgB  = WgA + (size_t)H * H;          // multiplies m
        const float* bg_i = bg + (size_t)i * H;
        const float* ga_i = gamma + (size_t)i * H;
        const float* be_i = beta + (size_t)i * H;

        neigh_kernel<<<nbW, 256>>>(cur, neigh, n);
        float* outp = (i == L - 1) ? out_h : other;
        tc_layer<<<nbT, 256, LSMEM_BYTES>>>(cur, neigh, Ws_i, bs_i, Wn_i, bn_i,
                                            WgA, WgB, bg_i, hp, ga_i, be_i, outp, n);
        other = cur;
        cur = outp;
    }

    // attention pooling over sinks
    tc_score<<<nbT, 256, SSMEM_BYTES>>>(cur, W_att, b_att, W_score, b_score, n);
    pool2_kernel<<<64, 256>>>(cur, n);
    finish_kernel<<<1, 128>>>(out_g);
}

// round 7
// speedup vs baseline: 3.2782x; 1.1059x over previous
#include <cuda_runtime.h>
#include <cuda_fp16.h>
#include <math.h>
#include <stdint.h>

#define MAXN 100000
#define MAXE 800000
#define H 128

// ---------------- device scratch ----------------
__device__ float g_hA[(size_t)MAXN * H];
__device__ float g_hB[(size_t)MAXN * H];
__device__ uint32_t g_hAh[(size_t)MAXN * 64];   // half2 k-pair mirrors
__device__ uint32_t g_hBh[(size_t)MAXN * 64];
__device__ uint32_t g_ngh[(size_t)MAXN * 64];
__device__ uint4 g_Wh4[16 * 2048];              // preconverted weight panels (half2 kpair)
__device__ int   g_indeg[MAXN];
__device__ int   g_outdeg[MAXN];
__device__ int   g_cursor[MAXN];
__device__ int   g_off[MAXN];
__device__ int   g_csr[MAXE];
__device__ int   g_bsum[128];
__device__ float g_hp[MAXN];
__device__ float g_invdeg[MAXN];
__device__ float g_scores[MAXN];
__device__ float g_emb[H];
__device__ float g_sumexp;
__device__ unsigned g_maxbits;

__device__ __forceinline__ float neg_inf() { return __int_as_float(0xff800000); }
__device__ __forceinline__ unsigned encf(float f) {
    unsigned u = __float_as_uint(f);
    return (u & 0x80000000u) ? ~u : (u | 0x80000000u);
}
__device__ __forceinline__ float decf(unsigned u) {
    return (u & 0x80000000u) ? __uint_as_float(u ^ 0x80000000u) : __uint_as_float(~u);
}

// ---------------- fp16 helpers ----------------
__device__ __forceinline__ uint32_t f2h2(float a, float b) {
    __half2 h = __floats2half2_rn(a, b);
    return *(uint32_t*)&h;
}
__device__ __forceinline__ float2 h2f2(uint32_t u) {
    __half2 h = *(__half2*)&u;
    return __half22float2(h);
}
__device__ __forceinline__ void mma16816(float* c, uint32_t a0, uint32_t a1, uint32_t a2, uint32_t a3,
                                         uint32_t b0, uint32_t b1) {
    asm volatile("mma.sync.aligned.m16n8k16.row.col.f32.f16.f16.f32 "
                 "{%0,%1,%2,%3}, {%4,%5,%6,%7}, {%8,%9}, {%0,%1,%2,%3};"
                 : "+f"(c[0]), "+f"(c[1]), "+f"(c[2]), "+f"(c[3])
                 : "r"(a0), "r"(a1), "r"(a2), "r"(a3), "r"(b0), "r"(b1));
}
__device__ __forceinline__ uint32_t smem_u32(const void* p) {
    uint32_t a;
    asm("{ .reg .u64 t; cvta.to.shared.u64 t, %1; cvt.u32.u64 %0, t; }" : "=r"(a) : "l"(p));
    return a;
}
#define CP_COMMIT() asm volatile("cp.async.commit_group;" ::: "memory")
#define CP_WAIT0()  asm volatile("cp.async.wait_group 0;" ::: "memory")

// A tile: 128 rows x 64 half2, stride 68 u32.  W tile: 64 kp-rows x 128 half2, stride 136 u32.
#define AP_STRIDE 68
#define WP_STRIDE 136
#define SZ_AP (128 * AP_STRIDE)
#define SZ_WP (64 * WP_STRIDE)
#define GSMEM_BYTES ((SZ_AP + SZ_WP + 128) * 4)
#define SSMEM_BYTES ((SZ_AP + SZ_WP + 512) * 4)
#define LSMEM_BYTES ((2 * SZ_AP + SZ_WP + 640 + 512) * 4)

// ---------------- tile loaders (512-thread CTAs) ----------------
// fp32 A rows -> half tile (input projection only)
__device__ __forceinline__ void load_a_f32(const float4* __restrict__ G, int r0, int n, uint32_t* sm) {
    int t = threadIdx.x;
#pragma unroll
    for (int i = 0; i < 8; i++) {
        int g = t + i * 512;
        int row = g >> 5, c4 = g & 31;
        float4 v = make_float4(0.f, 0.f, 0.f, 0.f);
        if (r0 + row < n) v = G[(size_t)(r0 + row) * 32 + c4];
        uint2 w;
        w.x = f2h2(v.x, v.y);
        w.y = f2h2(v.z, v.w);
        *(uint2*)(sm + row * AP_STRIDE + c4 * 2) = w;
    }
}
// async copy of half A tile (2048 x 16B)
__device__ __forceinline__ void copy_a_async(const uint32_t* __restrict__ src, int r0, int n, uint32_t dstb) {
    int t = threadIdx.x;
#pragma unroll
    for (int i = 0; i < 4; i++) {
        int g = t + i * 512;
        int row = g >> 4, q = g & 15;
        uint32_t dst = dstb + (uint32_t)(row * AP_STRIDE + q * 4) * 4u;
        const uint32_t* s = src + (size_t)(r0 + row) * 64 + q * 4;
        int sz = (r0 + row < n) ? 16 : 0;
        asm volatile("cp.async.cg.shared.global [%0], [%1], 16, %2;" :: "r"(dst), "l"(s), "r"(sz));
    }
}
// async copy of half W panel (2048 x 16B)
__device__ __forceinline__ void copy_w_async(const uint4* __restrict__ src, uint32_t dstb) {
    int t = threadIdx.x;
#pragma unroll
    for (int i = 0; i < 4; i++) {
        int g = t + i * 512;
        int kp = g >> 5, c4 = g & 31;
        uint32_t dst = dstb + (uint32_t)(kp * WP_STRIDE + c4 * 4) * 4u;
        asm volatile("cp.async.cg.shared.global [%0], [%1], 16;" :: "r"(dst), "l"(src + kp * 32 + c4));
    }
}

// warp-tile MMA: 16 warps, each 16 rows x 64 cols -> acc[8][4]
__device__ __forceinline__ void mma_tile(const uint32_t* AP, const uint32_t* WP,
                                         float acc[8][4], int warpM, int warpN,
                                         int gid, int tq) {
    int rb = warpM * 16;
#pragma unroll
    for (int ks = 0; ks < 8; ks++) {
        int kp0 = ks * 8;
        uint32_t a0 = AP[(rb + gid) * AP_STRIDE + kp0 + tq];
        uint32_t a1 = AP[(rb + gid + 8) * AP_STRIDE + kp0 + tq];
        uint32_t a2 = AP[(rb + gid) * AP_STRIDE + kp0 + tq + 4];
        uint32_t a3 = AP[(rb + gid + 8) * AP_STRIDE + kp0 + tq + 4];
#pragma unroll
        for (int nt = 0; nt < 8; nt++) {
            int cb = warpN * 64 + nt * 8 + gid;
            uint32_t b0 = WP[(kp0 + tq) * WP_STRIDE + cb];
            uint32_t b1 = WP[(kp0 + tq + 4) * WP_STRIDE + cb];
            mma16816(acc[nt], a0, a1, a2, a3, b0, b1);
        }
    }
}

// ---------------- weight preconversion ----------------
__global__ void wconv_kernel(const float* __restrict__ W_in, const float* __restrict__ Ws,
                             const float* __restrict__ Wn, const float* __restrict__ Wg,
                             const float* __restrict__ W_att, int L) {
    int idx = blockIdx.x * blockDim.x + threadIdx.x;
    int total = (4 * L + 2) * 8192;
    if (idx >= total) return;
    int p = idx >> 13;
    int j = idx & 8191;
    int kp = j >> 7, nn = j & 127;
    const float* src;
    if (p == 0) src = W_in;
    else if (p <= L) src = Ws + (size_t)(p - 1) * H * H;
    else if (p <= 2 * L) src = Wn + (size_t)(p - 1 - L) * H * H;
    else if (p <= 3 * L) src = Wg + (size_t)(p - 1 - 2 * L) * 2 * H * H;
    else if (p <= 4 * L) src = Wg + (size_t)(p - 1 - 3 * L) * 2 * H * H + (size_t)H * H;
    else src = W_att;
    ((uint32_t*)g_Wh4)[idx] = f2h2(src[(size_t)(2 * kp) * H + nn], src[(size_t)(2 * kp + 1) * H + nn]);
}

// ---------------- GEMM (input projection): C = A@W + bias, + half mirror ----------------
__global__ __launch_bounds__(512) void tc_gemm(
    const float* __restrict__ A, const uint4* __restrict__ Wp,
    const float* __restrict__ bias, float* __restrict__ C, uint32_t* __restrict__ Ch, int n)
{
    extern __shared__ uint32_t smem[];
    uint32_t* AP = smem;
    uint32_t* WP = smem + SZ_AP;
    float* sb = (float*)(smem + SZ_AP + SZ_WP);
    uint32_t sbase = smem_u32(smem);

    int tid = threadIdx.x, wid = tid >> 5, lane = tid & 31;
    int warpM = wid >> 1, warpN = wid & 1, gid = lane >> 2, tq = lane & 3;
    int r0 = blockIdx.x * 128;

    copy_w_async(Wp, sbase + SZ_AP * 4);
    CP_COMMIT();
    load_a_f32((const float4*)A, r0, n, AP);
    if (tid < 128) sb[tid] = bias[tid];
    CP_WAIT0();
    __syncthreads();

    float acc[8][4];
#pragma unroll
    for (int nt = 0; nt < 8; nt++)
#pragma unroll
        for (int j = 0; j < 4; j++) acc[nt][j] = 0.f;

    mma_tile(AP, WP, acc, warpM, warpN, gid, tq);

#pragma unroll
    for (int p = 0; p < 2; p++) {
        int row = r0 + warpM * 16 + p * 8 + gid;
        if (row >= n) continue;
#pragma unroll
        for (int nt = 0; nt < 8; nt++) {
            int cb = warpN * 64 + nt * 8 + 2 * tq;
            float2 o;
            o.x = acc[nt][2 * p + 0] + sb[cb];
            o.y = acc[nt][2 * p + 1] + sb[cb + 1];
            *(float2*)(C + (size_t)row * H + cb) = o;
            Ch[(size_t)row * 64 + (cb >> 1)] = f2h2(o.x, o.y);
        }
    }
}

// ---------------- fused layer kernel ----------------
__global__ __launch_bounds__(512) void tc_layer(
    const float* __restrict__ curf, const uint32_t* __restrict__ curh,
    const uint32_t* __restrict__ ngh,
    const uint4* __restrict__ Wsp, const uint4* __restrict__ Wnp,
    const uint4* __restrict__ WgAp, const uint4* __restrict__ WgBp,
    const float* __restrict__ bs, const float* __restrict__ bn, const float* __restrict__ bg,
    const float* __restrict__ coef,
    const float* __restrict__ gamma, const float* __restrict__ beta,
    float* __restrict__ Houtf, uint32_t* __restrict__ Houth, int n)
{
    extern __shared__ uint32_t smem[];
    uint32_t* Acur = smem;
    uint32_t* WP   = smem + SZ_AP;
    uint32_t* Am   = smem + SZ_AP + SZ_WP;
    float* sc  = (float*)(smem + 2 * SZ_AP + SZ_WP);  // bs|bn|bg|gamma|beta
    float* lnb = sc + 640;
    uint32_t sbase = smem_u32(smem);
    uint32_t wpb = sbase + SZ_AP * 4;

    int tid = threadIdx.x, wid = tid >> 5, lane = tid & 31;
    int warpM = wid >> 1, warpN = wid & 1, gid = lane >> 2, tq = lane & 3;
    int r0 = blockIdx.x * 128;

    copy_a_async(curh, r0, n, sbase);
    copy_a_async(ngh, r0, n, sbase + (SZ_AP + SZ_WP) * 4);
    copy_w_async(Wsp, wpb);
    if (tid < 128) {
        sc[tid] = bs[tid]; sc[128 + tid] = bn[tid]; sc[256 + tid] = bg[tid];
        sc[384 + tid] = gamma[tid]; sc[512 + tid] = beta[tid];
    }
    CP_COMMIT(); CP_WAIT0();
    __syncthreads();

    float acc1[8][4];
#pragma unroll
    for (int nt = 0; nt < 8; nt++)
#pragma unroll
        for (int j = 0; j < 4; j++) acc1[nt][j] = 0.f;

    mma_tile(Acur, WP, acc1, warpM, warpN, gid, tq);        // cur@Ws
    __syncthreads();
    copy_w_async(Wnp, wpb);
    CP_COMMIT(); CP_WAIT0();
    __syncthreads();
    mma_tile(Am, WP, acc1, warpM, warpN, gid, tq);          // += neigh@Wn
    __syncthreads();                                        // Am & WP reads done

    // m = acc1 + bs + cf*bn (exact fp32 in regs); write half m over Am; prefetch WgA
    copy_w_async(WgAp, wpb);
    CP_COMMIT();
#pragma unroll
    for (int p = 0; p < 2; p++) {
        int lrow = warpM * 16 + p * 8 + gid;
        int row = r0 + lrow;
        if (row >= n) continue;
        float cf = coef[row];
#pragma unroll
        for (int nt = 0; nt < 8; nt++) {
            int cb = warpN * 64 + nt * 8 + 2 * tq;
            float v0 = acc1[nt][2 * p + 0] + sc[cb + 0] + cf * sc[128 + cb + 0];
            float v1 = acc1[nt][2 * p + 1] + sc[cb + 1] + cf * sc[128 + cb + 1];
            acc1[nt][2 * p + 0] = v0;
            acc1[nt][2 * p + 1] = v1;
            Am[lrow * AP_STRIDE + (cb >> 1)] = f2h2(v0, v1);
        }
    }
    CP_WAIT0();
    __syncthreads();

    float acc2[8][4];
#pragma unroll
    for (int nt = 0; nt < 8; nt++)
#pragma unroll
        for (int j = 0; j < 4; j++) acc2[nt][j] = 0.f;

    mma_tile(Acur, WP, acc2, warpM, warpN, gid, tq);        // cur@WgA
    __syncthreads();
    copy_w_async(WgBp, wpb);
    CP_COMMIT(); CP_WAIT0();
    __syncthreads();
    mma_tile(Am, WP, acc2, warpM, warpN, gid, tq);          // += m@WgB

    // epilogue: gate + blend (exact fp32 h) + LN + ReLU
    float rsum[2] = {0.f, 0.f};
    float rsq[2] = {0.f, 0.f};
#pragma unroll
    for (int p = 0; p < 2; p++) {
        int row = r0 + warpM * 16 + p * 8 + gid;
        if (row >= n) continue;
        const float* hrow = curf + (size_t)row * H;
#pragma unroll
        for (int nt = 0; nt < 8; nt++) {
            int cb = warpN * 64 + nt * 8 + 2 * tq;
            float2 hv = *(const float2*)(hrow + cb);
            float pre, g, v;
            pre = acc2[nt][2 * p + 0] + sc[256 + cb];
            g = 1.f / (1.f + expf(-pre));
            v = g * acc1[nt][2 * p + 0] + (1.f - g) * hv.x;
            acc1[nt][2 * p + 0] = v; rsum[p] += v; rsq[p] += v * v;
            pre = acc2[nt][2 * p + 1] + sc[256 + cb + 1];
            g = 1.f / (1.f + expf(-pre));
            v = g * acc1[nt][2 * p + 1] + (1.f - g) * hv.y;
            acc1[nt][2 * p + 1] = v; rsum[p] += v; rsq[p] += v * v;
        }
    }
#pragma unroll
    for (int p = 0; p < 2; p++) {
        rsum[p] += __shfl_xor_sync(0xffffffffu, rsum[p], 1);
        rsum[p] += __shfl_xor_sync(0xffffffffu, rsum[p], 2);
        rsq[p] += __shfl_xor_sync(0xffffffffu, rsq[p], 1);
        rsq[p] += __shfl_xor_sync(0xffffffffu, rsq[p], 2);
    }
    if (tq == 0) {
#pragma unroll
        for (int p = 0; p < 2; p++) {
            int lrow = warpM * 16 + p * 8 + gid;
            lnb[lrow * 4 + warpN * 2 + 0] = rsum[p];
            lnb[lrow * 4 + warpN * 2 + 1] = rsq[p];
        }
    }
    __syncthreads();
#pragma unroll
    for (int p = 0; p < 2; p++) {
        int lrow = warpM * 16 + p * 8 + gid;
        int row = r0 + lrow;
        if (row >= n) continue;
        float sum = lnb[lrow * 4 + 0] + lnb[lrow * 4 + 2];
        float sq  = lnb[lrow * 4 + 1] + lnb[lrow * 4 + 3];
        float mu = sum * (1.f / 128.f);
        float var = sq * (1.f / 128.f) - mu * mu;
        float rs = rsqrtf(var + 1e-5f);
        float* orow = Houtf + (size_t)row * H;
#pragma unroll
        for (int nt = 0; nt < 8; nt++) {
            int cb = warpN * 64 + nt * 8 + 2 * tq;
            float2 o;
            o.x = fmaxf(fmaf((acc1[nt][2 * p + 0] - mu) * rs, sc[384 + cb], sc[512 + cb]), 0.f);
            o.y = fmaxf(fmaf((acc1[nt][2 * p + 1] - mu) * rs, sc[384 + cb + 1], sc[512 + cb + 1]), 0.f);
            *(float2*)(orow + cb) = o;
            Houth[(size_t)row * 64 + (cb >> 1)] = f2h2(o.x, o.y);
        }
    }
}

// ---------------- fused attention score ----------------
__global__ __launch_bounds__(512) void tc_score(
    const uint32_t* __restrict__ Ah, const uint4* __restrict__ Wp,
    const float* __restrict__ bias, const float* __restrict__ Wsc,
    const float* __restrict__ bsc, int n)
{
    extern __shared__ uint32_t smem[];
    uint32_t* AP = smem;
    uint32_t* WP = smem + SZ_AP;
    float* sb = (float*)(smem + SZ_AP + SZ_WP);
    float* sw = sb + 128;
    float* lnb = sw + 128;
    uint32_t sbase = smem_u32(smem);

    int tid = threadIdx.x, wid = tid >> 5, lane = tid & 31;
    int warpM = wid >> 1, warpN = wid & 1, gid = lane >> 2, tq = lane & 3;
    int r0 = blockIdx.x * 128;

    copy_a_async(Ah, r0, n, sbase);
    copy_w_async(Wp, sbase + SZ_AP * 4);
    if (tid < 128) sb[tid] = bias[tid];
    else if (tid < 256) sw[tid - 128] = Wsc[tid - 128];
    CP_COMMIT(); CP_WAIT0();
    __syncthreads();

    float acc[8][4];
#pragma unroll
    for (int nt = 0; nt < 8; nt++)
#pragma unroll
        for (int j = 0; j < 4; j++) acc[nt][j] = 0.f;

    mma_tile(AP, WP, acc, warpM, warpN, gid, tq);

    float part[2] = {0.f, 0.f};
#pragma unroll
    for (int nt = 0; nt < 8; nt++) {
        int cb = warpN * 64 + nt * 8 + 2 * tq;
#pragma unroll
        for (int p = 0; p < 2; p++) {
            part[p] += tanhf(acc[nt][2 * p + 0] + sb[cb]) * sw[cb];
            part[p] += tanhf(acc[nt][2 * p + 1] + sb[cb + 1]) * sw[cb + 1];
        }
    }
#pragma unroll
    for (int p = 0; p < 2; p++) {
        part[p] += __shfl_xor_sync(0xffffffffu, part[p], 1);
        part[p] += __shfl_xor_sync(0xffffffffu, part[p], 2);
    }
    if (tq == 0) {
#pragma unroll
        for (int p = 0; p < 2; p++) {
            int lrow = warpM * 16 + p * 8 + gid;
            lnb[lrow * 2 + warpN] = part[p];
        }
    }
    __syncthreads();
    if (warpN == 0 && tq == 0) {
#pragma unroll
        for (int p = 0; p < 2; p++) {
            int lrow = warpM * 16 + p * 8 + gid;
            int row = r0 + lrow;
            if (row >= n) continue;
            float scv = lnb[lrow * 2 + 0] + lnb[lrow * 2 + 1] + bsc[0];
            bool sink = (g_outdeg[row] == 0);
            g_scores[row] = sink ? scv : neg_inf();
            if (sink) atomicMax(&g_maxbits, encf(scv));
        }
    }
}

// ---------------- graph prep ----------------
__global__ void zero_kernel(int n) {
    int i = blockIdx.x * blockDim.x + threadIdx.x;
    if (i < n) { g_indeg[i] = 0; g_outdeg[i] = 0; g_cursor[i] = 0; }
    if (i < H) g_emb[i] = 0.f;
    if (i == 0) { g_maxbits = encf(neg_inf()); g_sumexp = 0.f; }
}
__global__ void deg_kernel(const int* __restrict__ src, const int* __restrict__ dst, int e) {
    int i = blockIdx.x * blockDim.x + threadIdx.x;
    if (i < e) { atomicAdd(&g_indeg[dst[i]], 1); atomicAdd(&g_outdeg[src[i]], 1); }
}
__global__ void prep_kernel(int n) {
    int i = blockIdx.x * blockDim.x + threadIdx.x;
    if (i < n) {
        int d = g_indeg[i];
        g_hp[i] = d > 0 ? 1.f : 0.f;
        g_invdeg[i] = 1.f / (float)(d > 0 ? d : 1);
    }
}
__global__ void scan1_kernel(int n) {
    __shared__ int sm[1024];
    int t = threadIdx.x;
    int i = blockIdx.x * 1024 + t;
    int v = (i < n) ? g_indeg[i] : 0;
    sm[t] = v;
    __syncthreads();
    for (int off = 1; off < 1024; off <<= 1) {
        int x = (t >= off) ? sm[t - off] : 0;
        __syncthreads();
        sm[t] += x;
        __syncthreads();
    }
    if (i < n) g_off[i] = sm[t] - v;
    if (t == 1023) g_bsum[blockIdx.x] = sm[1023];
}
__global__ void scan2_kernel(int nb) {
    if (threadIdx.x == 0) {
        int c = 0;
        for (int i = 0; i < nb; i++) { int x = g_bsum[i]; g_bsum[i] = c; c += x; }
    }
}
__global__ void scan3_kernel(int n) {
    int i = blockIdx.x * blockDim.x + threadIdx.x;
    if (i < n) g_off[i] += g_bsum[i >> 10];
}
__global__ void fill_kernel(const int* __restrict__ src, const int* __restrict__ dst, int e) {
    int i = blockIdx.x * blockDim.x + threadIdx.x;
    if (i < e) {
        int d = dst[i];
        int p = g_off[d] + atomicAdd(&g_cursor[d], 1);
        g_csr[p] = src[i];
    }
}

// ---------------- neighbor mean (half in, half out, fp32 accumulate) ----------------
__global__ void neigh_kernel(const uint32_t* __restrict__ Hh, uint32_t* __restrict__ Ngh, int n) {
    int gw = (blockIdx.x * blockDim.x + threadIdx.x) >> 5;
    int lane = threadIdx.x & 31;
    if (gw >= n) return;
    int start = g_off[gw];
    int deg = g_indeg[gw];
    const uint2* H2 = (const uint2*)Hh;   // 32 uint2 per row
    float4 acc = make_float4(0.f, 0.f, 0.f, 0.f);
    for (int base = 0; base < deg; base += 32) {
        int e = base + lane;
        int s = (e < deg) ? g_csr[start + e] : 0;
        int cnt = min(32, deg - base);
        for (int j = 0; j < cnt; j++) {
            int sj = __shfl_sync(0xffffffffu, s, j);
            uint2 v = H2[(size_t)sj * 32 + lane];
            float2 f0 = h2f2(v.x), f1 = h2f2(v.y);
            acc.x += f0.x; acc.y += f0.y; acc.z += f1.x; acc.w += f1.y;
        }
    }
    float iv = g_invdeg[gw];
    uint2 o;
    o.x = f2h2(acc.x * iv, acc.y * iv);
    o.y = f2h2(acc.z * iv, acc.w * iv);
    ((uint2*)Ngh)[(size_t)gw * 32 + lane] = o;
}

// ---------------- pooling ----------------
__global__ void pool2_kernel(const float* __restrict__ Hin, int n) {
    __shared__ float sb[8 * 128];
    __shared__ float se[8];
    int tid = threadIdx.x, w = tid >> 5, lane = tid & 31;
    int gw = (blockIdx.x * blockDim.x + tid) >> 5;
    int nw = (gridDim.x * blockDim.x) >> 5;
    float mx = decf(g_maxbits);
    const float4* H4 = (const float4*)Hin;
    float4 acc = make_float4(0.f, 0.f, 0.f, 0.f);
    float es = 0.f;
    for (int i = gw; i < n; i += nw) {
        float s = g_scores[i];
        if (s >= -1e30f) {
            float e = expf(s - mx);
            if (lane == 0) es += e;
            float4 hv = H4[(size_t)i * 32 + lane];
            acc.x += e * hv.x; acc.y += e * hv.y; acc.z += e * hv.z; acc.w += e * hv.w;
        }
    }
    *(float4*)&sb[w * 128 + lane * 4] = acc;
    if (lane == 0) se[w] = es;
    __syncthreads();
    if (tid < 128) {
        float t = 0.f;
#pragma unroll
        for (int j = 0; j < 8; j++) t += sb[j * 128 + tid];
        if (t != 0.f) atomicAdd(&g_emb[tid], t);
    }
    if (tid == 0) {
        float t = 0.f;
#pragma unroll
        for (int j = 0; j < 8; j++) t += se[j];
        if (t != 0.f) atomicAdd(&g_sumexp, t);
    }
}
__global__ void finish_kernel(float* __restrict__ gout) {
    int t = threadIdx.x;
    gout[t] = g_emb[t] / g_sumexp;
}

// ---------------- launch ----------------
extern "C" void kernel_launch(void* const* d_in, const int* in_sizes, int n_in,
                              void* d_out, int out_size)
{
    const float* node_feats = (const float*)d_in[0];
    const int*   src        = (const int*)d_in[1];
    const int*   dst        = (const int*)d_in[2];
    const float* W_in       = (const float*)d_in[3];
    const float* b_in       = (const float*)d_in[4];
    const float* Ws         = (const float*)d_in[5];
    const float* bs         = (const float*)d_in[6];
    const float* Wn         = (const float*)d_in[7];
    const float* bn         = (const float*)d_in[8];
    const float* Wg         = (const float*)d_in[9];
    const float* bg         = (const float*)d_in[10];
    const float* gamma      = (const float*)d_in[11];
    const float* beta       = (const float*)d_in[12];
    const float* W_att      = (const float*)d_in[13];
    const float* b_att      = (const float*)d_in[14];
    const float* W_score    = (const float*)d_in[15];
    const float* b_score    = (const float*)d_in[16];

    int n = in_sizes[0] / H;
    int e = in_sizes[1];
    int L = in_sizes[6] / H;

    float* out_h = (float*)d_out;
    float* out_g = out_h + (size_t)n * H;

    float *hA, *hB, *hp;
    uint32_t *hAh, *hBh, *ngh;
    uint4* Wh;
    cudaGetSymbolAddress((void**)&hA, g_hA);
    cudaGetSymbolAddress((void**)&hB, g_hB);
    cudaGetSymbolAddress((void**)&hAh, g_hAh);
    cudaGetSymbolAddress((void**)&hBh, g_hBh);
    cudaGetSymbolAddress((void**)&ngh, g_ngh);
    cudaGetSymbolAddress((void**)&hp, g_hp);
    cudaGetSymbolAddress((void**)&Wh, g_Wh4);

    cudaFuncSetAttribute(tc_gemm,  cudaFuncAttributeMaxDynamicSharedMemorySize, GSMEM_BYTES);
    cudaFuncSetAttribute(tc_score, cudaFuncAttributeMaxDynamicSharedMemorySize, SSMEM_BYTES);
    cudaFuncSetAttribute(tc_layer, cudaFuncAttributeMaxDynamicSharedMemorySize, LSMEM_BYTES);

    int nbN = (n + 255) / 256;
    int nbE = (e + 255) / 256;
    int nbT = (n + 127) / 128;
    int nbW = (n + 7) / 8;
    int nbS = (n + 1023) / 1024;
    int wtotal = (4 * L + 2) * 8192;

    // weight conversion + graph prep
    wconv_kernel<<<(wtotal + 255) / 256, 256>>>(W_in, Ws, Wn, Wg, W_att, L);
    zero_kernel<<<nbN, 256>>>(n);
    deg_kernel<<<nbE, 256>>>(src, dst, e);
    prep_kernel<<<nbN, 256>>>(n);
    scan1_kernel<<<nbS, 1024>>>(n);
    scan2_kernel<<<1, 32>>>(nbS);
    scan3_kernel<<<nbN, 256>>>(n);
    fill_kernel<<<nbE, 256>>>(src, dst, e);

    // input projection (panel 0)
    tc_gemm<<<nbT, 512, GSMEM_BYTES>>>(node_feats, Wh + 0 * 2048, b_in, hA, hAh, n);

    float* cur = hA;       uint32_t* curh = hAh;
    float* other = hB;     uint32_t* otherh = hBh;
    for (int i = 0; i < L; i++) {
        const uint4* Wsp  = Wh + (size_t)(1 + i) * 2048;
        const uint4* Wnp  = Wh + (size_t)(1 + L + i) * 2048;
        const uint4* WgAp = Wh + (size_t)(1 + 2 * L + i) * 2048;
        const uint4* WgBp = Wh + (size_t)(1 + 3 * L + i) * 2048;
        const float* bs_i = bs + (size_t)i * H;
        const float* bn_i = bn + (size_t)i * H;
        const float* bg_i = bg + (size_t)i * H;
        const float* ga_i = gamma + (size_t)i * H;
        const float* be_i = beta + (size_t)i * H;

        neigh_kernel<<<nbW, 256>>>(curh, ngh, n);
        float* outp = (i == L - 1) ? out_h : other;
        tc_layer<<<nbT, 512, LSMEM_BYTES>>>(cur, curh, ngh, Wsp, Wnp, WgAp, WgBp,
                                            bs_i, bn_i, bg_i, hp, ga_i, be_i, outp, otherh, n);
        other = cur;
        cur = outp;
        uint32_t* th = curh; curh = otherh; otherh = th;
    }

    // attention pooling over sinks (panel 4L+1)
    tc_score<<<nbT, 512, SSMEM_BYTES>>>(curh, Wh + (size_t)(4 * L + 1) * 2048,
                                        b_att, W_score, b_score, n);
    pool2_kernel<<<64, 256>>>(cur, n);
    finish_kernel<<<1, 128>>>(out_g);
}